// round 5
// baseline (speedup 1.0000x reference)
#include <cuda_runtime.h>
#include <math_constants.h>
#include <cstdint>

#define NTOK 4096      // B*S
#define DIM  1024
#define HEADS 16
#define HDIM 64
#define SEQ  2048
#define BATCH 2

// Scratch (allocation-free requirement -> __device__ globals)
__device__ float g_q[NTOK * DIM];
__device__ float g_k[NTOK * DIM];
__device__ float g_v[NTOK * DIM];
__device__ float g_vt[NTOK * DIM];        // V transposed: [B][H][HDIM][SEQ]
__device__ float g_ctx[NTOK * DIM];

// ===========================================================================
// Helpers
// ===========================================================================
__device__ __forceinline__ float f2tf32(float f) {
    uint32_t u;
    asm("cvt.rna.tf32.f32 %0, %1;" : "=r"(u) : "f"(f));
    return __uint_as_float(u);
}
__device__ __forceinline__ uint32_t f2tf32u(float f) {
    uint32_t u;
    asm("cvt.rna.tf32.f32 %0, %1;" : "=r"(u) : "f"(f));
    return u;
}

__device__ __forceinline__ float ex2f(float x) {
    float y;
    asm("ex2.approx.ftz.f32 %0, %1;" : "=f"(y) : "f"(x));
    return y;
}

#define CP_ASYNC16(smem_addr, gmem_ptr) \
    asm volatile("cp.async.cg.shared.global [%0], [%1], 16;" \
                 :: "r"((uint32_t)(smem_addr)), "l"(gmem_ptr) : "memory")
#define CP_COMMIT() asm volatile("cp.async.commit_group;" ::: "memory")
#define CP_WAIT(n)  asm volatile("cp.async.wait_group %0;" :: "n"(n) : "memory")

__device__ __forceinline__ uint32_t smem_u32(const void* p) {
    uint32_t a;
    asm("{ .reg .u64 t; cvta.to.shared.u64 t, %1; cvt.u32.u64 %0, t; }"
        : "=r"(a) : "l"(p));
    return a;
}

// mma.sync m16n8k8 tf32
__device__ __forceinline__ void mma_tf32(
    float* d, const uint32_t* a, const uint32_t* b)
{
    asm volatile(
        "mma.sync.aligned.m16n8k8.row.col.f32.tf32.tf32.f32 "
        "{%0,%1,%2,%3}, {%4,%5,%6,%7}, {%8,%9}, {%0,%1,%2,%3};"
        : "+f"(d[0]), "+f"(d[1]), "+f"(d[2]), "+f"(d[3])
        : "r"(a[0]), "r"(a[1]), "r"(a[2]), "r"(a[3]),
          "r"(b[0]), "r"(b[1]));
}

// ===========================================================================
// GEMM v2:  C[z] = A @ W[z] + bias[z]     (A:[4096,1024], W:[1024,1024])
//  - W read directly row-major [K][N]; both fragments tf32-rounded in-register
//  - CTA tile 256x128, BK=32, 512 threads (16 warps of 32x64), 2-stage
//  - gridDim.z selects (W, bias, C) -> QKV fused in one launch
// ===========================================================================
#define GDIM 1024
#define ASTR_G 36                 // A smem row stride (floats)
#define BSTR_G 136                // B smem row stride (floats): 136%32=8 -> bank 8t+g
#define A_STAGE_F (256 * ASTR_G)  // 9216 floats
#define B_STAGE_F (32 * BSTR_G)   // 4352 floats
#define STAGE_F   (A_STAGE_F + B_STAGE_F)
#define GEMM_SMEM_BYTES (2 * STAGE_F * 4)   // 108544 B

__global__ void __launch_bounds__(512, 1) gemm_mma_kernel(
    const float* __restrict__ A,
    const float* __restrict__ W0, const float* __restrict__ W1,
    const float* __restrict__ W2,
    const float* __restrict__ b0p, const float* __restrict__ b1p,
    const float* __restrict__ b2p,
    float* __restrict__ C0, float* __restrict__ C1, float* __restrict__ C2,
    int round_out)
{
    extern __shared__ __align__(16) float sm[];
    float* sA[2] = { sm,                       sm + STAGE_F };
    float* sB[2] = { sm + A_STAGE_F,           sm + STAGE_F + A_STAGE_F };

    const int z = blockIdx.z;
    const float* W    = (z == 0) ? W0 : (z == 1) ? W1 : W2;
    const float* bias = (z == 0) ? b0p : (z == 1) ? b1p : b2p;
    float*       C    = (z == 0) ? C0 : (z == 1) ? C1 : C2;

    const int tid  = threadIdx.x;
    const int wid  = tid >> 5;          // 0..15
    const int lane = tid & 31;
    const int g    = lane >> 2;
    const int t    = lane & 3;
    const int wm   = wid >> 1;          // 0..7  -> rows wm*32
    const int wn   = wid & 1;           // 0..1  -> cols wn*64

    const int brow = blockIdx.y * 256;
    const int bcol = blockIdx.x * 128;

    const uint32_t sAu[2] = { smem_u32(sA[0]), smem_u32(sA[1]) };
    const uint32_t sBu[2] = { smem_u32(sB[0]), smem_u32(sB[1]) };

    // A loader: 4 chunks: idx = tid + i*512 -> r = idx>>3 (0..255), c = idx&7
    const int ar = tid >> 3;            // 0..63 (+64*i)
    const int ac = tid & 7;
    const float* Asrc = A + (size_t)(brow + ar) * GDIM + ac * 4;
    // B loader: 2 chunks: idx = tid + i*512 -> row = idx>>5 (0..31), coln = (idx&31)*4
    const int br = tid >> 5;            // 0..15 (+16*i)
    const int bc = (tid & 31) << 2;

    auto load_stage = [&](int s, int k0) {
#pragma unroll
        for (int i = 0; i < 4; i++) {
            const int r = ar + i * 64;
            const uint32_t off = (uint32_t)(r * ASTR_G + ac * 4) * 4u;
            CP_ASYNC16(sAu[s] + off, Asrc + (size_t)(i * 64) * GDIM + k0);
        }
#pragma unroll
        for (int i = 0; i < 2; i++) {
            const int r = br + i * 16;
            const uint32_t off = (uint32_t)(r * BSTR_G + bc) * 4u;
            CP_ASYNC16(sBu[s] + off, W + (size_t)(k0 + r) * GDIM + bcol + bc);
        }
        CP_COMMIT();
    };

    float acc[2][8][4];
#pragma unroll
    for (int mi = 0; mi < 2; mi++)
#pragma unroll
        for (int ni = 0; ni < 8; ni++)
#pragma unroll
            for (int c = 0; c < 4; c++) acc[mi][ni][c] = 0.f;

    load_stage(0, 0);

    for (int kt = 0; kt < GDIM / 32; ++kt) {
        const int cur = kt & 1;
        CP_WAIT(0);
        __syncthreads();
        if (kt + 1 < GDIM / 32) load_stage(cur ^ 1, (kt + 1) * 32);

        const float* a_s = sA[cur];
        const float* b_s = sB[cur];

#pragma unroll
        for (int ks = 0; ks < 4; ks++) {
            const int k0 = ks * 8;
            uint32_t af[2][4];
#pragma unroll
            for (int mi = 0; mi < 2; mi++) {
                const int row = wm * 32 + mi * 16;
                af[mi][0] = f2tf32u(a_s[(row + g)     * ASTR_G + k0 + t]);
                af[mi][1] = f2tf32u(a_s[(row + g + 8) * ASTR_G + k0 + t]);
                af[mi][2] = f2tf32u(a_s[(row + g)     * ASTR_G + k0 + t + 4]);
                af[mi][3] = f2tf32u(a_s[(row + g + 8) * ASTR_G + k0 + t + 4]);
            }
            uint32_t bf[8][2];
#pragma unroll
            for (int ni = 0; ni < 8; ni++) {
                const int n = wn * 64 + ni * 8 + g;
                bf[ni][0] = f2tf32u(b_s[(k0 + t)     * BSTR_G + n]);
                bf[ni][1] = f2tf32u(b_s[(k0 + t + 4) * BSTR_G + n]);
            }
#pragma unroll
            for (int mi = 0; mi < 2; mi++)
#pragma unroll
                for (int ni = 0; ni < 8; ni++)
                    mma_tf32(acc[mi][ni], af[mi], bf[ni]);
        }
    }

    // Epilogue: bias + optional tf32 rounding + float2 stores
#pragma unroll
    for (int ni = 0; ni < 8; ni++) {
        const int col = bcol + wn * 64 + ni * 8 + t * 2;
        const float2 bv = *reinterpret_cast<const float2*>(&bias[col]);
#pragma unroll
        for (int mi = 0; mi < 2; mi++) {
            const int r0 = brow + wm * 32 + mi * 16 + g;
            float2 v0, v1;
            v0.x = acc[mi][ni][0] + bv.x;
            v0.y = acc[mi][ni][1] + bv.y;
            v1.x = acc[mi][ni][2] + bv.x;
            v1.y = acc[mi][ni][3] + bv.y;
            if (round_out) {
                v0.x = f2tf32(v0.x); v0.y = f2tf32(v0.y);
                v1.x = f2tf32(v1.x); v1.y = f2tf32(v1.y);
            }
            *reinterpret_cast<float2*>(&C[(size_t)r0 * GDIM + col])       = v0;
            *reinterpret_cast<float2*>(&C[(size_t)(r0 + 8) * GDIM + col]) = v1;
        }
    }
}

// ===========================================================================
// V transpose: v [B,S,H*64] -> vt [B,H,64,SEQ]
// ===========================================================================
__global__ void vt_transpose_kernel(const float* __restrict__ v,
                                    float* __restrict__ vt)
{
    __shared__ float t[32][33];
    const int bh = blockIdx.z;
    const int b  = bh >> 4;
    const int h  = bh & 15;
    const int s0 = blockIdx.x * 32;
    const int d0 = blockIdx.y * 32;
#pragma unroll
    for (int j = 0; j < 32; j += 8)
        t[threadIdx.y + j][threadIdx.x] =
            v[(size_t)(b * SEQ + s0 + threadIdx.y + j) * DIM + h * HDIM + d0 + threadIdx.x];
    __syncthreads();
#pragma unroll
    for (int j = 0; j < 32; j += 8)
        vt[((size_t)bh * HDIM + d0 + threadIdx.y + j) * SEQ + s0 + threadIdx.x] =
            t[threadIdx.x][threadIdx.y + j];
}

// ===========================================================================
// Flash attention, mma.sync tf32 (unchanged from R4).
// ===========================================================================
#define ASTR 68
#define ATTN_SMEM_FLOATS (128 * ASTR + 64 * ASTR + 64 * ASTR + 128 * ASTR)
#define ATTN_SMEM_BYTES  (ATTN_SMEM_FLOATS * 4)

__global__ void __launch_bounds__(256, 2) attn_mma_kernel(
    const float* __restrict__ Q, const float* __restrict__ K,
    const float* __restrict__ Vt, float* __restrict__ O)
{
    extern __shared__ __align__(16) float sm[];
    float* sQ  = sm;                        // [128][ASTR]
    float* sK  = sQ + 128 * ASTR;           // [64][ASTR]
    float* sVt = sK + 64 * ASTR;            // [64][ASTR]
    float* sP  = sVt + 64 * ASTR;           // [128][ASTR]

    const uint32_t sKu  = smem_u32(sK);
    const uint32_t sVtu = smem_u32(sVt);

    const int tid  = threadIdx.x;
    const int wid  = tid >> 5;
    const int lane = tid & 31;
    const int g    = lane >> 2;
    const int t    = lane & 3;
    const int wm   = wid * 16;

    const int q0 = blockIdx.x * 128;
    const int h  = blockIdx.y;
    const int b  = blockIdx.z;
    const size_t rowbase = (size_t)b * SEQ;
    const int colbase = h * HDIM;
    const int bh = b * HEADS + h;

    const float cscale = 0.125f * 1.4426950408889634f;

#pragma unroll
    for (int i = 0; i < 8; i++) {
        int idx = tid + i * 256;
        int r   = idx >> 4;
        int d4  = (idx & 15) << 2;
        float4 v = *reinterpret_cast<const float4*>(
            &Q[(rowbase + q0 + r) * DIM + colbase + d4]);
        sQ[r * ASTR + d4 + 0] = f2tf32(v.x * cscale);
        sQ[r * ASTR + d4 + 1] = f2tf32(v.y * cscale);
        sQ[r * ASTR + d4 + 2] = f2tf32(v.z * cscale);
        sQ[r * ASTR + d4 + 3] = f2tf32(v.w * cscale);
    }

    float m0 = -CUDART_INF_F, m1 = -CUDART_INF_F;
    float l0 = 0.f, l1 = 0.f;
    float accO[8][4];
#pragma unroll
    for (int ni = 0; ni < 8; ni++)
#pragma unroll
        for (int c = 0; c < 4; c++) accO[ni][c] = 0.f;

    const int kr = tid >> 4;
    const int kc = (tid & 15) << 2;

    for (int t0 = 0; t0 < SEQ; t0 += 64) {
        __syncthreads();
#pragma unroll
        for (int i = 0; i < 4; i++) {
            int r = kr + i * 16;
            uint32_t off = (uint32_t)(r * ASTR + kc) * 4u;
            CP_ASYNC16(sKu + off,
                       &K[(rowbase + t0 + r) * DIM + colbase + kc]);
            CP_ASYNC16(sVtu + off,
                       &Vt[((size_t)bh * HDIM + r) * SEQ + t0 + kc]);
        }
        CP_COMMIT();
        CP_WAIT(0);
        __syncthreads();

        float sfr[8][4];
#pragma unroll
        for (int ni = 0; ni < 8; ni++)
#pragma unroll
            for (int c = 0; c < 4; c++) sfr[ni][c] = 0.f;

#pragma unroll
        for (int ks = 0; ks < 8; ks++) {
            const int k0 = ks * 8;
            uint32_t af[4];
            af[0] = __float_as_uint(sQ[(wm + g)     * ASTR + k0 + t]);
            af[1] = __float_as_uint(sQ[(wm + g + 8) * ASTR + k0 + t]);
            af[2] = __float_as_uint(sQ[(wm + g)     * ASTR + k0 + t + 4]);
            af[3] = __float_as_uint(sQ[(wm + g + 8) * ASTR + k0 + t + 4]);
#pragma unroll
            for (int ni = 0; ni < 8; ni++) {
                uint32_t bf[2];
                const int n = ni * 8 + g;
                bf[0] = __float_as_uint(sK[n * ASTR + k0 + t]);
                bf[1] = __float_as_uint(sK[n * ASTR + k0 + t + 4]);
                mma_tf32(sfr[ni], af, bf);
            }
        }

        float mt0 = sfr[0][0], mt1 = sfr[0][2];
#pragma unroll
        for (int ni = 0; ni < 8; ni++) {
            mt0 = fmaxf(mt0, fmaxf(sfr[ni][0], sfr[ni][1]));
            mt1 = fmaxf(mt1, fmaxf(sfr[ni][2], sfr[ni][3]));
        }
        mt0 = fmaxf(mt0, __shfl_xor_sync(0xffffffffu, mt0, 1));
        mt0 = fmaxf(mt0, __shfl_xor_sync(0xffffffffu, mt0, 2));
        mt1 = fmaxf(mt1, __shfl_xor_sync(0xffffffffu, mt1, 1));
        mt1 = fmaxf(mt1, __shfl_xor_sync(0xffffffffu, mt1, 2));

        const float mn0 = fmaxf(m0, mt0);
        const float mn1 = fmaxf(m1, mt1);
        const float al0 = ex2f(m0 - mn0);
        const float al1 = ex2f(m1 - mn1);
        m0 = mn0; m1 = mn1;

        float lt0 = 0.f, lt1 = 0.f;
#pragma unroll
        for (int ni = 0; ni < 8; ni++) {
            float p0 = ex2f(sfr[ni][0] - mn0);
            float p1 = ex2f(sfr[ni][1] - mn0);
            float p2 = ex2f(sfr[ni][2] - mn1);
            float p3 = ex2f(sfr[ni][3] - mn1);
            lt0 += p0 + p1;
            lt1 += p2 + p3;
            float2 w0 = make_float2(f2tf32(p0), f2tf32(p1));
            float2 w1 = make_float2(f2tf32(p2), f2tf32(p3));
            *reinterpret_cast<float2*>(&sP[(wm + g)     * ASTR + ni * 8 + 2 * t]) = w0;
            *reinterpret_cast<float2*>(&sP[(wm + g + 8) * ASTR + ni * 8 + 2 * t]) = w1;
        }
        lt0 += __shfl_xor_sync(0xffffffffu, lt0, 1);
        lt0 += __shfl_xor_sync(0xffffffffu, lt0, 2);
        lt1 += __shfl_xor_sync(0xffffffffu, lt1, 1);
        lt1 += __shfl_xor_sync(0xffffffffu, lt1, 2);
        l0 = l0 * al0 + lt0;
        l1 = l1 * al1 + lt1;

#pragma unroll
        for (int ni = 0; ni < 8; ni++) {
            accO[ni][0] *= al0; accO[ni][1] *= al0;
            accO[ni][2] *= al1; accO[ni][3] *= al1;
        }
        __syncwarp();

#pragma unroll
        for (int ks = 0; ks < 8; ks++) {
            const int k0 = ks * 8;
            uint32_t pf[4];
            pf[0] = __float_as_uint(sP[(wm + g)     * ASTR + k0 + t]);
            pf[1] = __float_as_uint(sP[(wm + g + 8) * ASTR + k0 + t]);
            pf[2] = __float_as_uint(sP[(wm + g)     * ASTR + k0 + t + 4]);
            pf[3] = __float_as_uint(sP[(wm + g + 8) * ASTR + k0 + t + 4]);
#pragma unroll
            for (int ni = 0; ni < 8; ni++) {
                uint32_t bf[2];
                const int n = ni * 8 + g;
                bf[0] = __float_as_uint(sVt[n * ASTR + k0 + t]);
                bf[1] = __float_as_uint(sVt[n * ASTR + k0 + t + 4]);
                mma_tf32(accO[ni], pf, bf);
            }
        }
    }

    const float inv0 = 1.f / l0;
    const float inv1 = 1.f / l1;
#pragma unroll
    for (int ni = 0; ni < 8; ni++) {
        const int col = colbase + ni * 8 + 2 * t;
        float2 o0, o1;
        o0.x = f2tf32(accO[ni][0] * inv0);
        o0.y = f2tf32(accO[ni][1] * inv0);
        o1.x = f2tf32(accO[ni][2] * inv1);
        o1.y = f2tf32(accO[ni][3] * inv1);
        *reinterpret_cast<float2*>(
            &O[(rowbase + q0 + wm + g) * DIM + col]) = o0;
        *reinterpret_cast<float2*>(
            &O[(rowbase + q0 + wm + g + 8) * DIM + col]) = o1;
    }
}

// ===========================================================================
extern "C" void kernel_launch(void* const* d_in, const int* in_sizes, int n_in,
                              void* d_out, int out_size)
{
    const float* x  = (const float*)d_in[0];
    const float* Wq = (const float*)d_in[1];
    const float* bq = (const float*)d_in[2];
    const float* Wk = (const float*)d_in[3];
    const float* bk = (const float*)d_in[4];
    const float* Wv = (const float*)d_in[5];
    const float* bv = (const float*)d_in[6];
    const float* Wo = (const float*)d_in[7];
    const float* bo = (const float*)d_in[8];
    float* out = (float*)d_out;

    float *q, *k, *v, *vt, *ctx;
    cudaGetSymbolAddress((void**)&q,   g_q);
    cudaGetSymbolAddress((void**)&k,   g_k);
    cudaGetSymbolAddress((void**)&v,   g_v);
    cudaGetSymbolAddress((void**)&vt,  g_vt);
    cudaGetSymbolAddress((void**)&ctx, g_ctx);

    cudaFuncSetAttribute(gemm_mma_kernel,
                         cudaFuncAttributeMaxDynamicSharedMemorySize,
                         GEMM_SMEM_BYTES);

    // 1) fused QKV projections (rounded outputs: feed tf32 attention mma)
    {
        dim3 gg(DIM / 128, NTOK / 256, 3);
        gemm_mma_kernel<<<gg, 512, GEMM_SMEM_BYTES>>>(
            x, Wq, Wk, Wv, bq, bk, bv, q, k, v, 1);
    }

    // 2) transpose V for the PV mma B-operand
    {
        dim3 tb(32, 8), tg(SEQ / 32, HDIM / 32, BATCH * HEADS);
        vt_transpose_kernel<<<tg, tb>>>(v, vt);
    }

    // 3) attention (mma.sync tf32 flash)
    cudaFuncSetAttribute(attn_mma_kernel,
                         cudaFuncAttributeMaxDynamicSharedMemorySize,
                         ATTN_SMEM_BYTES);
    attn_mma_kernel<<<dim3(SEQ / 128, HEADS, BATCH), 256, ATTN_SMEM_BYTES>>>(
        q, k, vt, ctx);

    // 4) output projection (fp32 output, no rounding)
    {
        dim3 gg(DIM / 128, NTOK / 256, 1);
        gemm_mma_kernel<<<gg, 512, GEMM_SMEM_BYTES>>>(
            ctx, Wo, Wo, Wo, bo, bo, bo, out, out, out, 0);
    }
}

// round 6
// speedup vs baseline: 1.0694x; 1.0694x over previous
#include <cuda_runtime.h>
#include <math_constants.h>
#include <cstdint>

#define NTOK 4096      // B*S
#define DIM  1024
#define HEADS 16
#define HDIM 64
#define SEQ  2048
#define BATCH 2

// Scratch (allocation-free requirement -> __device__ globals)
__device__ float g_q[NTOK * DIM];
__device__ float g_k[NTOK * DIM];
__device__ float g_v[NTOK * DIM];
__device__ float g_vt[NTOK * DIM];        // V transposed: [B][H][HDIM][SEQ]
__device__ float g_ctx[NTOK * DIM];
__device__ float g_xr[NTOK * DIM];        // tf32-rounded x
__device__ float g_wt[4 * DIM * DIM];     // transposed+rounded Wq,Wk,Wv,Wo

// ===========================================================================
// Helpers
// ===========================================================================
__device__ __forceinline__ float f2tf32(float f) {
    uint32_t u;
    asm("cvt.rna.tf32.f32 %0, %1;" : "=r"(u) : "f"(f));
    return __uint_as_float(u);
}

__device__ __forceinline__ float ex2f(float x) {
    float y;
    asm("ex2.approx.ftz.f32 %0, %1;" : "=f"(y) : "f"(x));
    return y;
}

#define CP_ASYNC16(smem_addr, gmem_ptr) \
    asm volatile("cp.async.cg.shared.global [%0], [%1], 16;" \
                 :: "r"((uint32_t)(smem_addr)), "l"(gmem_ptr) : "memory")
#define CP_COMMIT() asm volatile("cp.async.commit_group;" ::: "memory")
#define CP_WAIT(n)  asm volatile("cp.async.wait_group %0;" :: "n"(n) : "memory")

__device__ __forceinline__ uint32_t smem_u32(const void* p) {
    uint32_t a;
    asm("{ .reg .u64 t; cvta.to.shared.u64 t, %1; cvt.u32.u64 %0, t; }"
        : "=r"(a) : "l"(p));
    return a;
}

// mma.sync m16n8k8 tf32
__device__ __forceinline__ void mma_tf32(
    float* d, const uint32_t* a, const uint32_t* b)
{
    asm volatile(
        "mma.sync.aligned.m16n8k8.row.col.f32.tf32.tf32.f32 "
        "{%0,%1,%2,%3}, {%4,%5,%6,%7}, {%8,%9}, {%0,%1,%2,%3};"
        : "+f"(d[0]), "+f"(d[1]), "+f"(d[2]), "+f"(d[3])
        : "r"(a[0]), "r"(a[1]), "r"(a[2]), "r"(a[3]),
          "r"(b[0]), "r"(b[1]));
}

// ===========================================================================
// GEMM v3:  C[z] = A @ Wt[z]^T + bias[z]
//  A:[4096,1024] row-major (pre-rounded tf32);  Wt:[N][K] (pre-transposed,
//  pre-rounded).  CTA tile 128x128, BK=16, 256 threads (8 warps of 32x64),
//  3-stage cp.async ring with CP_WAIT(1), 2 CTAs/SM.
// ===========================================================================
#define GDIM 1024
#define BK3 16
#define STR3 20                     // smem row stride: 20%32=20 -> banks 20g+t distinct
#define HALF3 (128 * STR3)          // one operand per stage = 2560 floats
#define ST3_F (2 * HALF3)           // A+B per stage = 5120 floats
#define NSTAGE 3
#define GEMM_SMEM_BYTES (NSTAGE * ST3_F * 4)   // 61440 B

__global__ void __launch_bounds__(256, 2) gemm_mma_kernel(
    const float* __restrict__ A,
    const float* __restrict__ Wt0, const float* __restrict__ Wt1,
    const float* __restrict__ Wt2,
    const float* __restrict__ b0p, const float* __restrict__ b1p,
    const float* __restrict__ b2p,
    float* __restrict__ C0, float* __restrict__ C1, float* __restrict__ C2,
    int round_out)
{
    extern __shared__ __align__(16) float sm[];

    const int z = blockIdx.z;
    const float* Wt   = (z == 0) ? Wt0 : (z == 1) ? Wt1 : Wt2;
    const float* bias = (z == 0) ? b0p : (z == 1) ? b1p : b2p;
    float*       C    = (z == 0) ? C0 : (z == 1) ? C1 : C2;

    const int tid  = threadIdx.x;
    const int wid  = tid >> 5;          // 0..7
    const int lane = tid & 31;
    const int g    = lane >> 2;
    const int t    = lane & 3;
    const int wm   = wid >> 1;          // 0..3 -> rows wm*32
    const int wn   = wid & 1;           // 0..1 -> cols wn*64

    const int brow = blockIdx.y * 128;
    const int bcol = blockIdx.x * 128;

    const uint32_t smu = smem_u32(sm);

    // loader: 2 chunks per operand: idx = tid + i*256 -> r = idx>>2, c = idx&3
    const int lr = tid >> 2;            // 0..63 (+64*i)
    const int lc = tid & 3;             // 16B chunk within 16-float row

    const float* Asrc = A  + (size_t)(brow + lr) * GDIM + lc * 4;
    const float* Bsrc = Wt + (size_t)(bcol + lr) * GDIM + lc * 4;

    auto load_stage = [&](int s, int kt) {
        const int k0 = kt * BK3;
        const uint32_t base = smu + (uint32_t)(s * ST3_F) * 4u;
#pragma unroll
        for (int i = 0; i < 2; i++) {
            const int r = lr + i * 64;
            const uint32_t off = (uint32_t)(r * STR3 + lc * 4) * 4u;
            CP_ASYNC16(base + off, Asrc + (size_t)(i * 64) * GDIM + k0);
            CP_ASYNC16(base + HALF3 * 4u + off, Bsrc + (size_t)(i * 64) * GDIM + k0);
        }
        CP_COMMIT();
    };

    float acc[2][8][4];
#pragma unroll
    for (int mi = 0; mi < 2; mi++)
#pragma unroll
        for (int ni = 0; ni < 8; ni++)
#pragma unroll
            for (int c = 0; c < 4; c++) acc[mi][ni][c] = 0.f;

    load_stage(0, 0);
    load_stage(1, 1);

    const int NKT = GDIM / BK3;   // 64
    for (int kt = 0; kt < NKT; ++kt) {
        const int cur = kt % NSTAGE;
        CP_WAIT(1);
        __syncthreads();

        const float* a_s = sm + cur * ST3_F;
        const float* b_s = a_s + HALF3;

#pragma unroll
        for (int ks = 0; ks < 2; ks++) {
            const int k0 = ks * 8;
            uint32_t af[2][4];
#pragma unroll
            for (int mi = 0; mi < 2; mi++) {
                const int row = wm * 32 + mi * 16;
                af[mi][0] = __float_as_uint(a_s[(row + g)     * STR3 + k0 + t]);
                af[mi][1] = __float_as_uint(a_s[(row + g + 8) * STR3 + k0 + t]);
                af[mi][2] = __float_as_uint(a_s[(row + g)     * STR3 + k0 + t + 4]);
                af[mi][3] = __float_as_uint(a_s[(row + g + 8) * STR3 + k0 + t + 4]);
            }
            uint32_t bf[8][2];
#pragma unroll
            for (int ni = 0; ni < 8; ni++) {
                const int n = wn * 64 + ni * 8 + g;
                bf[ni][0] = __float_as_uint(b_s[n * STR3 + k0 + t]);
                bf[ni][1] = __float_as_uint(b_s[n * STR3 + k0 + t + 4]);
            }
#pragma unroll
            for (int mi = 0; mi < 2; mi++)
#pragma unroll
                for (int ni = 0; ni < 8; ni++)
                    mma_tf32(acc[mi][ni], af[mi], bf[ni]);
        }

        if (kt + 2 < NKT) load_stage((kt + 2) % NSTAGE, kt + 2);
    }

    // Epilogue: bias + optional tf32 rounding + float2 stores
#pragma unroll
    for (int ni = 0; ni < 8; ni++) {
        const int col = bcol + wn * 64 + ni * 8 + t * 2;
        const float2 bv = *reinterpret_cast<const float2*>(&bias[col]);
#pragma unroll
        for (int mi = 0; mi < 2; mi++) {
            const int r0 = brow + wm * 32 + mi * 16 + g;
            float2 v0, v1;
            v0.x = acc[mi][ni][0] + bv.x;
            v0.y = acc[mi][ni][1] + bv.y;
            v1.x = acc[mi][ni][2] + bv.x;
            v1.y = acc[mi][ni][3] + bv.y;
            if (round_out) {
                v0.x = f2tf32(v0.x); v0.y = f2tf32(v0.y);
                v1.x = f2tf32(v1.x); v1.y = f2tf32(v1.y);
            }
            *reinterpret_cast<float2*>(&C[(size_t)r0 * GDIM + col])       = v0;
            *reinterpret_cast<float2*>(&C[(size_t)(r0 + 8) * GDIM + col]) = v1;
        }
    }
}

// ===========================================================================
// Weight transpose + tf32 round: Wt[n][k] = rna(W[k][n]),  1024x1024
// ===========================================================================
__global__ void transpose_round_kernel(const float* __restrict__ W,
                                       float* __restrict__ Wt)
{
    __shared__ float t[32][33];
    int n = blockIdx.x * 32 + threadIdx.x;
    int k = blockIdx.y * 32 + threadIdx.y;
#pragma unroll
    for (int j = 0; j < 32; j += 8)
        t[threadIdx.y + j][threadIdx.x] = W[(size_t)(k + j) * DIM + n];
    __syncthreads();
    int ko = blockIdx.y * 32 + threadIdx.x;
    int no = blockIdx.x * 32 + threadIdx.y;
#pragma unroll
    for (int j = 0; j < 32; j += 8)
        Wt[(size_t)(no + j) * DIM + ko] = f2tf32(t[threadIdx.x][threadIdx.y + j]);
}

// tf32-round a big fp32 array (float4)
__global__ void round_tf32_kernel(const float4* __restrict__ in,
                                  float4* __restrict__ out, int n4)
{
    int i = blockIdx.x * blockDim.x + threadIdx.x;
    if (i < n4) {
        float4 v = in[i];
        v.x = f2tf32(v.x); v.y = f2tf32(v.y);
        v.z = f2tf32(v.z); v.w = f2tf32(v.w);
        out[i] = v;
    }
}

// ===========================================================================
// V transpose: v [B,S,H*64] -> vt [B,H,64,SEQ]
// ===========================================================================
__global__ void vt_transpose_kernel(const float* __restrict__ v,
                                    float* __restrict__ vt)
{
    __shared__ float t[32][33];
    const int bh = blockIdx.z;
    const int b  = bh >> 4;
    const int h  = bh & 15;
    const int s0 = blockIdx.x * 32;
    const int d0 = blockIdx.y * 32;
#pragma unroll
    for (int j = 0; j < 32; j += 8)
        t[threadIdx.y + j][threadIdx.x] =
            v[(size_t)(b * SEQ + s0 + threadIdx.y + j) * DIM + h * HDIM + d0 + threadIdx.x];
    __syncthreads();
#pragma unroll
    for (int j = 0; j < 32; j += 8)
        vt[((size_t)bh * HDIM + d0 + threadIdx.y + j) * SEQ + s0 + threadIdx.x] =
            t[threadIdx.x][threadIdx.y + j];
}

// ===========================================================================
// Flash attention, mma.sync tf32 (unchanged from R4/R5).
// ===========================================================================
#define ASTR 68
#define ATTN_SMEM_FLOATS (128 * ASTR + 64 * ASTR + 64 * ASTR + 128 * ASTR)
#define ATTN_SMEM_BYTES  (ATTN_SMEM_FLOATS * 4)

__global__ void __launch_bounds__(256, 2) attn_mma_kernel(
    const float* __restrict__ Q, const float* __restrict__ K,
    const float* __restrict__ Vt, float* __restrict__ O)
{
    extern __shared__ __align__(16) float sm[];
    float* sQ  = sm;                        // [128][ASTR]
    float* sK  = sQ + 128 * ASTR;           // [64][ASTR]
    float* sVt = sK + 64 * ASTR;            // [64][ASTR]
    float* sP  = sVt + 64 * ASTR;           // [128][ASTR]

    const uint32_t sKu  = smem_u32(sK);
    const uint32_t sVtu = smem_u32(sVt);

    const int tid  = threadIdx.x;
    const int wid  = tid >> 5;
    const int lane = tid & 31;
    const int g    = lane >> 2;
    const int t    = lane & 3;
    const int wm   = wid * 16;

    const int q0 = blockIdx.x * 128;
    const int h  = blockIdx.y;
    const int b  = blockIdx.z;
    const size_t rowbase = (size_t)b * SEQ;
    const int colbase = h * HDIM;
    const int bh = b * HEADS + h;

    const float cscale = 0.125f * 1.4426950408889634f;

#pragma unroll
    for (int i = 0; i < 8; i++) {
        int idx = tid + i * 256;
        int r   = idx >> 4;
        int d4  = (idx & 15) << 2;
        float4 v = *reinterpret_cast<const float4*>(
            &Q[(rowbase + q0 + r) * DIM + colbase + d4]);
        sQ[r * ASTR + d4 + 0] = f2tf32(v.x * cscale);
        sQ[r * ASTR + d4 + 1] = f2tf32(v.y * cscale);
        sQ[r * ASTR + d4 + 2] = f2tf32(v.z * cscale);
        sQ[r * ASTR + d4 + 3] = f2tf32(v.w * cscale);
    }

    float m0 = -CUDART_INF_F, m1 = -CUDART_INF_F;
    float l0 = 0.f, l1 = 0.f;
    float accO[8][4];
#pragma unroll
    for (int ni = 0; ni < 8; ni++)
#pragma unroll
        for (int c = 0; c < 4; c++) accO[ni][c] = 0.f;

    const int kr = tid >> 4;
    const int kc = (tid & 15) << 2;

    for (int t0 = 0; t0 < SEQ; t0 += 64) {
        __syncthreads();
#pragma unroll
        for (int i = 0; i < 4; i++) {
            int r = kr + i * 16;
            uint32_t off = (uint32_t)(r * ASTR + kc) * 4u;
            CP_ASYNC16(sKu + off,
                       &K[(rowbase + t0 + r) * DIM + colbase + kc]);
            CP_ASYNC16(sVtu + off,
                       &Vt[((size_t)bh * HDIM + r) * SEQ + t0 + kc]);
        }
        CP_COMMIT();
        CP_WAIT(0);
        __syncthreads();

        float sfr[8][4];
#pragma unroll
        for (int ni = 0; ni < 8; ni++)
#pragma unroll
            for (int c = 0; c < 4; c++) sfr[ni][c] = 0.f;

#pragma unroll
        for (int ks = 0; ks < 8; ks++) {
            const int k0 = ks * 8;
            uint32_t af[4];
            af[0] = __float_as_uint(sQ[(wm + g)     * ASTR + k0 + t]);
            af[1] = __float_as_uint(sQ[(wm + g + 8) * ASTR + k0 + t]);
            af[2] = __float_as_uint(sQ[(wm + g)     * ASTR + k0 + t + 4]);
            af[3] = __float_as_uint(sQ[(wm + g + 8) * ASTR + k0 + t + 4]);
#pragma unroll
            for (int ni = 0; ni < 8; ni++) {
                uint32_t bf[2];
                const int n = ni * 8 + g;
                bf[0] = __float_as_uint(sK[n * ASTR + k0 + t]);
                bf[1] = __float_as_uint(sK[n * ASTR + k0 + t + 4]);
                mma_tf32(sfr[ni], af, bf);
            }
        }

        float mt0 = sfr[0][0], mt1 = sfr[0][2];
#pragma unroll
        for (int ni = 0; ni < 8; ni++) {
            mt0 = fmaxf(mt0, fmaxf(sfr[ni][0], sfr[ni][1]));
            mt1 = fmaxf(mt1, fmaxf(sfr[ni][2], sfr[ni][3]));
        }
        mt0 = fmaxf(mt0, __shfl_xor_sync(0xffffffffu, mt0, 1));
        mt0 = fmaxf(mt0, __shfl_xor_sync(0xffffffffu, mt0, 2));
        mt1 = fmaxf(mt1, __shfl_xor_sync(0xffffffffu, mt1, 1));
        mt1 = fmaxf(mt1, __shfl_xor_sync(0xffffffffu, mt1, 2));

        const float mn0 = fmaxf(m0, mt0);
        const float mn1 = fmaxf(m1, mt1);
        const float al0 = ex2f(m0 - mn0);
        const float al1 = ex2f(m1 - mn1);
        m0 = mn0; m1 = mn1;

        float lt0 = 0.f, lt1 = 0.f;
#pragma unroll
        for (int ni = 0; ni < 8; ni++) {
            float p0 = ex2f(sfr[ni][0] - mn0);
            float p1 = ex2f(sfr[ni][1] - mn0);
            float p2 = ex2f(sfr[ni][2] - mn1);
            float p3 = ex2f(sfr[ni][3] - mn1);
            lt0 += p0 + p1;
            lt1 += p2 + p3;
            float2 w0 = make_float2(f2tf32(p0), f2tf32(p1));
            float2 w1 = make_float2(f2tf32(p2), f2tf32(p3));
            *reinterpret_cast<float2*>(&sP[(wm + g)     * ASTR + ni * 8 + 2 * t]) = w0;
            *reinterpret_cast<float2*>(&sP[(wm + g + 8) * ASTR + ni * 8 + 2 * t]) = w1;
        }
        lt0 += __shfl_xor_sync(0xffffffffu, lt0, 1);
        lt0 += __shfl_xor_sync(0xffffffffu, lt0, 2);
        lt1 += __shfl_xor_sync(0xffffffffu, lt1, 1);
        lt1 += __shfl_xor_sync(0xffffffffu, lt1, 2);
        l0 = l0 * al0 + lt0;
        l1 = l1 * al1 + lt1;

#pragma unroll
        for (int ni = 0; ni < 8; ni++) {
            accO[ni][0] *= al0; accO[ni][1] *= al0;
            accO[ni][2] *= al1; accO[ni][3] *= al1;
        }
        __syncwarp();

#pragma unroll
        for (int ks = 0; ks < 8; ks++) {
            const int k0 = ks * 8;
            uint32_t pf[4];
            pf[0] = __float_as_uint(sP[(wm + g)     * ASTR + k0 + t]);
            pf[1] = __float_as_uint(sP[(wm + g + 8) * ASTR + k0 + t]);
            pf[2] = __float_as_uint(sP[(wm + g)     * ASTR + k0 + t + 4]);
            pf[3] = __float_as_uint(sP[(wm + g + 8) * ASTR + k0 + t + 4]);
#pragma unroll
            for (int ni = 0; ni < 8; ni++) {
                uint32_t bf[2];
                const int n = ni * 8 + g;
                bf[0] = __float_as_uint(sVt[n * ASTR + k0 + t]);
                bf[1] = __float_as_uint(sVt[n * ASTR + k0 + t + 4]);
                mma_tf32(accO[ni], pf, bf);
            }
        }
    }

    const float inv0 = 1.f / l0;
    const float inv1 = 1.f / l1;
#pragma unroll
    for (int ni = 0; ni < 8; ni++) {
        const int col = colbase + ni * 8 + 2 * t;
        float2 o0, o1;
        o0.x = f2tf32(accO[ni][0] * inv0);
        o0.y = f2tf32(accO[ni][1] * inv0);
        o1.x = f2tf32(accO[ni][2] * inv1);
        o1.y = f2tf32(accO[ni][3] * inv1);
        *reinterpret_cast<float2*>(
            &O[(rowbase + q0 + wm + g) * DIM + col]) = o0;
        *reinterpret_cast<float2*>(
            &O[(rowbase + q0 + wm + g + 8) * DIM + col]) = o1;
    }
}

// ===========================================================================
extern "C" void kernel_launch(void* const* d_in, const int* in_sizes, int n_in,
                              void* d_out, int out_size)
{
    const float* x  = (const float*)d_in[0];
    const float* Wq = (const float*)d_in[1];
    const float* bq = (const float*)d_in[2];
    const float* Wk = (const float*)d_in[3];
    const float* bk = (const float*)d_in[4];
    const float* Wv = (const float*)d_in[5];
    const float* bv = (const float*)d_in[6];
    const float* Wo = (const float*)d_in[7];
    const float* bo = (const float*)d_in[8];
    float* out = (float*)d_out;

    float *q, *k, *v, *vt, *ctx, *xr, *wt;
    cudaGetSymbolAddress((void**)&q,   g_q);
    cudaGetSymbolAddress((void**)&k,   g_k);
    cudaGetSymbolAddress((void**)&v,   g_v);
    cudaGetSymbolAddress((void**)&vt,  g_vt);
    cudaGetSymbolAddress((void**)&ctx, g_ctx);
    cudaGetSymbolAddress((void**)&xr,  g_xr);
    cudaGetSymbolAddress((void**)&wt,  g_wt);
    float* wtq = wt;
    float* wtk = wt + DIM * DIM;
    float* wtv = wt + 2 * DIM * DIM;
    float* wto = wt + 3 * DIM * DIM;

    // 1) prep: round x, transpose+round weights (bit-identical numerics to
    //    in-register rounding, but removes all mainloop CVTs)
    {
        int n4 = NTOK * DIM / 4;
        round_tf32_kernel<<<(n4 + 255) / 256, 256>>>(
            (const float4*)x, (float4*)xr, n4);
        dim3 tb(32, 8), tg(DIM / 32, DIM / 32);
        transpose_round_kernel<<<tg, tb>>>(Wq, wtq);
        transpose_round_kernel<<<tg, tb>>>(Wk, wtk);
        transpose_round_kernel<<<tg, tb>>>(Wv, wtv);
        transpose_round_kernel<<<tg, tb>>>(Wo, wto);
    }

    cudaFuncSetAttribute(gemm_mma_kernel,
                         cudaFuncAttributeMaxDynamicSharedMemorySize,
                         GEMM_SMEM_BYTES);

    // 2) fused QKV projections
    {
        dim3 gg(DIM / 128, NTOK / 128, 3);
        gemm_mma_kernel<<<gg, 256, GEMM_SMEM_BYTES>>>(
            xr, wtq, wtk, wtv, bq, bk, bv, q, k, v, 1);
    }

    // 3) transpose V for the PV mma B-operand
    {
        dim3 tb(32, 8), tg(SEQ / 32, HDIM / 32, BATCH * HEADS);
        vt_transpose_kernel<<<tg, tb>>>(v, vt);
    }

    // 4) attention (mma.sync tf32 flash)
    cudaFuncSetAttribute(attn_mma_kernel,
                         cudaFuncAttributeMaxDynamicSharedMemorySize,
                         ATTN_SMEM_BYTES);
    attn_mma_kernel<<<dim3(SEQ / 128, HEADS, BATCH), 256, ATTN_SMEM_BYTES>>>(
        q, k, vt, ctx);

    // 5) output projection (fp32 output, no rounding)
    {
        dim3 gg(DIM / 128, NTOK / 128, 1);
        gemm_mma_kernel<<<gg, 256, GEMM_SMEM_BYTES>>>(
            ctx, wto, wto, wto, bo, bo, bo, out, out, out, 0);
    }
}

// round 7
// speedup vs baseline: 1.9062x; 1.7826x over previous
#include <cuda_runtime.h>
#include <cuda_fp16.h>
#include <math_constants.h>
#include <cstdint>

#define NTOK 4096      // B*S
#define DIM  1024
#define HEADS 16
#define HDIM 64
#define SEQ  2048
#define BATCH 2

// Scratch (allocation-free requirement -> __device__ globals), all fp16
__device__ __half g_xh[NTOK * DIM];
__device__ __half g_wth[4 * DIM * DIM];   // transposed fp16 Wq,Wk,Wv,Wo
__device__ __half g_qh[NTOK * DIM];
__device__ __half g_kh[NTOK * DIM];
__device__ __half g_vh[NTOK * DIM];
__device__ __half g_vth[NTOK * DIM];      // V transposed: [B][H][HDIM][SEQ]
__device__ __half g_ctxh[NTOK * DIM];

// ===========================================================================
// Helpers
// ===========================================================================
__device__ __forceinline__ float ex2f(float x) {
    float y;
    asm("ex2.approx.ftz.f32 %0, %1;" : "=f"(y) : "f"(x));
    return y;
}

#define CP_ASYNC16(smem_addr, gmem_ptr) \
    asm volatile("cp.async.cg.shared.global [%0], [%1], 16;" \
                 :: "r"((uint32_t)(smem_addr)), "l"(gmem_ptr) : "memory")
#define CP_COMMIT() asm volatile("cp.async.commit_group;" ::: "memory")
#define CP_WAIT(n)  asm volatile("cp.async.wait_group %0;" :: "n"(n) : "memory")

__device__ __forceinline__ uint32_t smem_u32(const void* p) {
    uint32_t a;
    asm("{ .reg .u64 t; cvta.to.shared.u64 t, %1; cvt.u32.u64 %0, t; }"
        : "=r"(a) : "l"(p));
    return a;
}

#define LDSM_X4(r0, r1, r2, r3, addr) \
    asm volatile("ldmatrix.sync.aligned.m8n8.x4.shared.b16 {%0,%1,%2,%3}, [%4];" \
                 : "=r"(r0), "=r"(r1), "=r"(r2), "=r"(r3) : "r"(addr))

// mma m16n8k16 fp16 in, fp32 accum
__device__ __forceinline__ void mma_f16(
    float* d, const uint32_t* a, const uint32_t* b)
{
    asm volatile(
        "mma.sync.aligned.m16n8k16.row.col.f32.f16.f16.f32 "
        "{%0,%1,%2,%3}, {%4,%5,%6,%7}, {%8,%9}, {%0,%1,%2,%3};"
        : "+f"(d[0]), "+f"(d[1]), "+f"(d[2]), "+f"(d[3])
        : "r"(a[0]), "r"(a[1]), "r"(a[2]), "r"(a[3]),
          "r"(b[0]), "r"(b[1]));
}

// ===========================================================================
// fp16 GEMM:  C[z] = A @ Wt[z]^T + bias[z]
//  A:[4096,1024] fp16 row-major;  Wt:[N][K] fp16.
//  CTA tile 128x128, BK=32 halves, 256 thr (8 warps of 32x64), 3-stage
//  cp.async ring (CP_WAIT(1)), 2 CTAs/SM. Smem row stride 40 halves:
//  LDSM row banks (r*20)%32 all distinct -> conflict-free.
// ===========================================================================
#define GDIM 1024
#define BKH 32
#define STRH 40
#define HALFH (128 * STRH)          // halves per operand per stage (5120)
#define STH   (2 * HALFH)           // halves per stage
#define NSTG  3
#define GEMM_SMEM_BYTES (NSTG * STH * 2)   // 61440 B

__global__ void __launch_bounds__(256, 2) gemm_h_kernel(
    const __half* __restrict__ A,
    const __half* __restrict__ Wt0, const __half* __restrict__ Wt1,
    const __half* __restrict__ Wt2,
    const float* __restrict__ b0p, const float* __restrict__ b1p,
    const float* __restrict__ b2p,
    void* __restrict__ C0, void* __restrict__ C1, void* __restrict__ C2,
    int out_half)
{
    extern __shared__ __align__(16) __half smh[];

    const int z = blockIdx.z;
    const __half* Wt   = (z == 0) ? Wt0 : (z == 1) ? Wt1 : Wt2;
    const float*  bias = (z == 0) ? b0p : (z == 1) ? b1p : b2p;
    void*         Cv   = (z == 0) ? C0 : (z == 1) ? C1 : C2;

    const int tid  = threadIdx.x;
    const int wid  = tid >> 5;
    const int lane = tid & 31;
    const int g    = lane >> 2;
    const int t    = lane & 3;
    const int lrow = lane & 7;
    const int sub  = lane >> 3;      // 0..3
    const int wm   = wid >> 1;       // 0..3
    const int wn   = wid & 1;        // 0..1

    const int brow = blockIdx.y * 128;
    const int bcol = blockIdx.x * 128;

    const uint32_t smu = smem_u32(smh);

    // per-thread ldmatrix coordinates
    const int arow_l = wm * 32 + lrow + ((sub & 1) << 3);   // + mi*16
    const int akoff  = (sub >> 1) << 3;                     // + ks*16
    const int bn_l   = wn * 64 + lrow + ((sub >> 1) << 3);  // + pi*16
    const int bkoff  = (sub & 1) << 3;                      // + ks*16

    // loader: row lr (0..127), half-chunks at lcb, lcb+8
    const int lr  = tid >> 1;
    const int lcb = (tid & 1) * 16;
    const __half* Asrc = A  + (size_t)(brow + lr) * GDIM + lcb;
    const __half* Bsrc = Wt + (size_t)(bcol + lr) * GDIM + lcb;
    const uint32_t loff = (uint32_t)(lr * STRH + lcb) * 2u;

    auto load_stage = [&](int s, int kt) {
        const int k0 = kt * BKH;
        const uint32_t base = smu + (uint32_t)(s * STH) * 2u;
        CP_ASYNC16(base + loff,                   Asrc + k0);
        CP_ASYNC16(base + loff + 16,              Asrc + k0 + 8);
        CP_ASYNC16(base + HALFH * 2u + loff,      Bsrc + k0);
        CP_ASYNC16(base + HALFH * 2u + loff + 16, Bsrc + k0 + 8);
        CP_COMMIT();
    };

    float acc[2][8][4];
#pragma unroll
    for (int mi = 0; mi < 2; mi++)
#pragma unroll
        for (int ni = 0; ni < 8; ni++)
#pragma unroll
            for (int c = 0; c < 4; c++) acc[mi][ni][c] = 0.f;

    load_stage(0, 0);
    load_stage(1, 1);

    const int NKT = GDIM / BKH;   // 32
    for (int kt = 0; kt < NKT; ++kt) {
        const int cur = kt % NSTG;
        CP_WAIT(1);
        __syncthreads();

        const uint32_t aBase = smu + (uint32_t)(cur * STH) * 2u;
        const uint32_t bBase = aBase + HALFH * 2u;

#pragma unroll
        for (int ks = 0; ks < 2; ks++) {
            uint32_t af[2][4];
#pragma unroll
            for (int mi = 0; mi < 2; mi++) {
                const uint32_t a = aBase +
                    (uint32_t)((arow_l + mi * 16) * STRH + ks * 16 + akoff) * 2u;
                LDSM_X4(af[mi][0], af[mi][1], af[mi][2], af[mi][3], a);
            }
            uint32_t bf[8][2];
#pragma unroll
            for (int pi = 0; pi < 4; pi++) {
                const uint32_t a = bBase +
                    (uint32_t)((bn_l + pi * 16) * STRH + ks * 16 + bkoff) * 2u;
                uint32_t r0, r1, r2, r3;
                LDSM_X4(r0, r1, r2, r3, a);
                bf[2 * pi][0] = r0; bf[2 * pi][1] = r1;
                bf[2 * pi + 1][0] = r2; bf[2 * pi + 1][1] = r3;
            }
#pragma unroll
            for (int mi = 0; mi < 2; mi++)
#pragma unroll
                for (int ni = 0; ni < 8; ni++)
                    mma_f16(acc[mi][ni], af[mi], bf[ni]);
        }

        if (kt + 2 < NKT) load_stage((kt + 2) % NSTG, kt + 2);
    }

    // Epilogue
#pragma unroll
    for (int ni = 0; ni < 8; ni++) {
        const int col = bcol + wn * 64 + ni * 8 + t * 2;
        const float2 bv = *reinterpret_cast<const float2*>(&bias[col]);
#pragma unroll
        for (int mi = 0; mi < 2; mi++) {
            const int r0 = brow + wm * 32 + mi * 16 + g;
            float2 v0, v1;
            v0.x = acc[mi][ni][0] + bv.x;
            v0.y = acc[mi][ni][1] + bv.y;
            v1.x = acc[mi][ni][2] + bv.x;
            v1.y = acc[mi][ni][3] + bv.y;
            if (out_half) {
                __half* C = (__half*)Cv;
                *reinterpret_cast<__half2*>(&C[(size_t)r0 * GDIM + col]) =
                    __floats2half2_rn(v0.x, v0.y);
                *reinterpret_cast<__half2*>(&C[(size_t)(r0 + 8) * GDIM + col]) =
                    __floats2half2_rn(v1.x, v1.y);
            } else {
                float* C = (float*)Cv;
                *reinterpret_cast<float2*>(&C[(size_t)r0 * GDIM + col])       = v0;
                *reinterpret_cast<float2*>(&C[(size_t)(r0 + 8) * GDIM + col]) = v1;
            }
        }
    }
}

// ===========================================================================
// Prep kernels
// ===========================================================================
__global__ void f2h_kernel(const float2* __restrict__ in,
                           __half2* __restrict__ out, int n2)
{
    int i = blockIdx.x * blockDim.x + threadIdx.x;
    if (i < n2) {
        float2 v = in[i];
        out[i] = __floats2half2_rn(v.x, v.y);
    }
}

// W float [K][N] -> Wth half [N][K]
__global__ void transpose_h_kernel(const float* __restrict__ W,
                                   __half* __restrict__ Wt)
{
    __shared__ float t[32][33];
    int n = blockIdx.x * 32 + threadIdx.x;
    int k = blockIdx.y * 32 + threadIdx.y;
#pragma unroll
    for (int j = 0; j < 32; j += 8)
        t[threadIdx.y + j][threadIdx.x] = W[(size_t)(k + j) * DIM + n];
    __syncthreads();
    int ko = blockIdx.y * 32 + threadIdx.x;
    int no = blockIdx.x * 32 + threadIdx.y;
#pragma unroll
    for (int j = 0; j < 32; j += 8)
        Wt[(size_t)(no + j) * DIM + ko] = __float2half_rn(t[threadIdx.x][threadIdx.y + j]);
}

// v half [B,S,H*64] -> vt half [B,H,64,SEQ]
__global__ void vt_transpose_h_kernel(const __half* __restrict__ v,
                                      __half* __restrict__ vt)
{
    __shared__ __half t[32][33];
    const int bh = blockIdx.z;
    const int b  = bh >> 4;
    const int h  = bh & 15;
    const int s0 = blockIdx.x * 32;
    const int d0 = blockIdx.y * 32;
#pragma unroll
    for (int j = 0; j < 32; j += 8)
        t[threadIdx.y + j][threadIdx.x] =
            v[(size_t)(b * SEQ + s0 + threadIdx.y + j) * DIM + h * HDIM + d0 + threadIdx.x];
    __syncthreads();
#pragma unroll
    for (int j = 0; j < 32; j += 8)
        vt[((size_t)bh * HDIM + d0 + threadIdx.y + j) * SEQ + s0 + threadIdx.x] =
            t[threadIdx.x][threadIdx.y + j];
}

// ===========================================================================
// fp16 flash attention.  Per CTA: 128 queries x one (b,h); 8 warps of 16 rows.
// 64-key tiles, double-buffered K/Vt, ldmatrix fragments, fp32 softmax.
// Softmax scale applied to the fp32 QK^T accumulator.
// ===========================================================================
#define QSTR 72                       // halves per smem row; (r*36)%32 distinct
#define SQ_OFF   0
#define SP_OFF   (128 * QSTR)
#define SK_OFF   (2 * 128 * QSTR)
#define KVBUF    (64 * QSTR)
#define SVT_OFF  (SK_OFF + 2 * KVBUF)
#define ATTN_SMEM_BYTES ((2 * 128 * QSTR + 4 * KVBUF) * 2)   // 73728 B

__global__ void __launch_bounds__(256, 2) attn_h_kernel(
    const __half* __restrict__ Q, const __half* __restrict__ K,
    const __half* __restrict__ Vt, __half* __restrict__ O)
{
    extern __shared__ __align__(16) __half smh[];
    const uint32_t smu = smem_u32(smh);
    __half* sP = smh + SP_OFF;

    const int tid  = threadIdx.x;
    const int wid  = tid >> 5;
    const int lane = tid & 31;
    const int g    = lane >> 2;
    const int t    = lane & 3;
    const int lrow = lane & 7;
    const int sub  = lane >> 3;
    const int wm   = wid * 16;

    const int q0 = blockIdx.x * 128;
    const int h  = blockIdx.y;
    const int b  = blockIdx.z;
    const size_t rowbase = (size_t)b * SEQ;
    const int colbase = h * HDIM;
    const int bh = b * HEADS + h;

    const float cscale = 0.125f * 1.4426950408889634f;  // 1/sqrt(64)*log2(e)

    // ldmatrix per-thread coordinates
    const int arow_l = lrow + ((sub & 1) << 3);          // A rows (+ base)
    const int akoff  = (sub >> 1) << 3;                  // A k offset (+ ks*16)
    const int bn_l   = lrow + ((sub >> 1) << 3);         // B n (+ pi*16)
    const int bkoff  = (sub & 1) << 3;                   // B k offset (+ ks*16)

    // ---- stage Q (raw fp16, 128 rows x 64 halves): 4 chunks per thread ----
    {
        const int qr  = tid >> 1;
        const int qc  = (tid & 1) * 32;
        const __half* src = &Q[(rowbase + q0 + qr) * DIM + colbase + qc];
        const uint32_t dst = smu + (uint32_t)(qr * QSTR + qc) * 2u;
#pragma unroll
        for (int i = 0; i < 4; i++)
            CP_ASYNC16(dst + i * 16, src + i * 8);
    }

    // ---- K/V tile loader (2 chunks per thread per operand) ----
    const int kr = tid >> 2;
    const int kc = (tid & 3) * 16;
    auto load_kv = [&](int s, int t0) {
        const uint32_t kdst = smu + (uint32_t)((SK_OFF + s * KVBUF) + kr * QSTR + kc) * 2u;
        const uint32_t vdst = smu + (uint32_t)((SVT_OFF + s * KVBUF) + kr * QSTR + kc) * 2u;
        const __half* ksrc = &K[(rowbase + t0 + kr) * DIM + colbase + kc];
        const __half* vsrc = &Vt[((size_t)bh * HDIM + kr) * SEQ + t0 + kc];
        CP_ASYNC16(kdst,      ksrc);
        CP_ASYNC16(kdst + 16, ksrc + 8);
        CP_ASYNC16(vdst,      vsrc);
        CP_ASYNC16(vdst + 16, vsrc + 8);
        CP_COMMIT();
    };

    load_kv(0, 0);   // commits Q loads too

    float m0 = -CUDART_INF_F, m1 = -CUDART_INF_F;
    float l0 = 0.f, l1 = 0.f;
    float accO[8][4];
#pragma unroll
    for (int ni = 0; ni < 8; ni++)
#pragma unroll
        for (int c = 0; c < 4; c++) accO[ni][c] = 0.f;

    for (int t0 = 0; t0 < SEQ; t0 += 64) {
        const int cur = (t0 >> 6) & 1;
        CP_WAIT(0);
        __syncthreads();
        if (t0 + 64 < SEQ) load_kv(cur ^ 1, t0 + 64);

        const uint32_t kBase = smu + (uint32_t)(SK_OFF + cur * KVBUF) * 2u;
        const uint32_t vBase = smu + (uint32_t)(SVT_OFF + cur * KVBUF) * 2u;

        // ---- S = Q @ K^T (fp32 accum) ----
        float sfr[8][4];
#pragma unroll
        for (int ni = 0; ni < 8; ni++)
#pragma unroll
            for (int c = 0; c < 4; c++) sfr[ni][c] = 0.f;

#pragma unroll
        for (int ks = 0; ks < 4; ks++) {
            uint32_t af[4];
            {
                const uint32_t a = smu +
                    (uint32_t)((wm + arow_l) * QSTR + ks * 16 + akoff) * 2u;
                LDSM_X4(af[0], af[1], af[2], af[3], a);
            }
#pragma unroll
            for (int pi = 0; pi < 4; pi++) {
                const uint32_t a = kBase +
                    (uint32_t)((bn_l + pi * 16) * QSTR + ks * 16 + bkoff) * 2u;
                uint32_t r0, r1, r2, r3;
                LDSM_X4(r0, r1, r2, r3, a);
                uint32_t bf0[2] = { r0, r1 }, bf1[2] = { r2, r3 };
                mma_f16(sfr[2 * pi],     af, bf0);
                mma_f16(sfr[2 * pi + 1], af, bf1);
            }
        }

        // ---- online softmax (scale applied to fp32 scores) ----
        float mt0 = sfr[0][0], mt1 = sfr[0][2];
#pragma unroll
        for (int ni = 0; ni < 8; ni++) {
            mt0 = fmaxf(mt0, fmaxf(sfr[ni][0], sfr[ni][1]));
            mt1 = fmaxf(mt1, fmaxf(sfr[ni][2], sfr[ni][3]));
        }
        mt0 = fmaxf(mt0, __shfl_xor_sync(0xffffffffu, mt0, 1));
        mt0 = fmaxf(mt0, __shfl_xor_sync(0xffffffffu, mt0, 2));
        mt1 = fmaxf(mt1, __shfl_xor_sync(0xffffffffu, mt1, 1));
        mt1 = fmaxf(mt1, __shfl_xor_sync(0xffffffffu, mt1, 2));
        mt0 *= cscale;
        mt1 *= cscale;

        const float mn0 = fmaxf(m0, mt0);
        const float mn1 = fmaxf(m1, mt1);
        const float al0 = ex2f(m0 - mn0);
        const float al1 = ex2f(m1 - mn1);
        m0 = mn0; m1 = mn1;

        float lt0 = 0.f, lt1 = 0.f;
#pragma unroll
        for (int ni = 0; ni < 8; ni++) {
            float p0 = ex2f(sfr[ni][0] * cscale - mn0);
            float p1 = ex2f(sfr[ni][1] * cscale - mn0);
            float p2 = ex2f(sfr[ni][2] * cscale - mn1);
            float p3 = ex2f(sfr[ni][3] * cscale - mn1);
            lt0 += p0 + p1;
            lt1 += p2 + p3;
            *reinterpret_cast<__half2*>(&sP[(wm + g) * QSTR + ni * 8 + 2 * t]) =
                __floats2half2_rn(p0, p1);
            *reinterpret_cast<__half2*>(&sP[(wm + g + 8) * QSTR + ni * 8 + 2 * t]) =
                __floats2half2_rn(p2, p3);
        }
        lt0 += __shfl_xor_sync(0xffffffffu, lt0, 1);
        lt0 += __shfl_xor_sync(0xffffffffu, lt0, 2);
        lt1 += __shfl_xor_sync(0xffffffffu, lt1, 1);
        lt1 += __shfl_xor_sync(0xffffffffu, lt1, 2);
        l0 = l0 * al0 + lt0;
        l1 = l1 * al1 + lt1;

#pragma unroll
        for (int ni = 0; ni < 8; ni++) {
            accO[ni][0] *= al0; accO[ni][1] *= al0;
            accO[ni][2] *= al1; accO[ni][3] *= al1;
        }
        __syncwarp();   // sP rows are warp-private

        // ---- O += P @ V ----
#pragma unroll
        for (int ks = 0; ks < 4; ks++) {
            uint32_t pf[4];
            {
                const uint32_t a = smu +
                    (uint32_t)(SP_OFF * 2) +
                    (uint32_t)((wm + arow_l) * QSTR + ks * 16 + akoff) * 2u;
                LDSM_X4(pf[0], pf[1], pf[2], pf[3], a);
            }
#pragma unroll
            for (int pi = 0; pi < 4; pi++) {
                const uint32_t a = vBase +
                    (uint32_t)((bn_l + pi * 16) * QSTR + ks * 16 + bkoff) * 2u;
                uint32_t r0, r1, r2, r3;
                LDSM_X4(r0, r1, r2, r3, a);
                uint32_t bf0[2] = { r0, r1 }, bf1[2] = { r2, r3 };
                mma_f16(accO[2 * pi],     pf, bf0);
                mma_f16(accO[2 * pi + 1], pf, bf1);
            }
        }
        __syncwarp();   // done reading sP before next tile overwrites it
    }

    // ---- normalize + write ctx (fp16, feeds Wo GEMM) ----
    const float inv0 = 1.f / l0;
    const float inv1 = 1.f / l1;
#pragma unroll
    for (int ni = 0; ni < 8; ni++) {
        const int col = colbase + ni * 8 + 2 * t;
        *reinterpret_cast<__half2*>(&O[(rowbase + q0 + wm + g) * DIM + col]) =
            __floats2half2_rn(accO[ni][0] * inv0, accO[ni][1] * inv0);
        *reinterpret_cast<__half2*>(&O[(rowbase + q0 + wm + g + 8) * DIM + col]) =
            __floats2half2_rn(accO[ni][2] * inv1, accO[ni][3] * inv1);
    }
}

// ===========================================================================
extern "C" void kernel_launch(void* const* d_in, const int* in_sizes, int n_in,
                              void* d_out, int out_size)
{
    const float* x  = (const float*)d_in[0];
    const float* Wq = (const float*)d_in[1];
    const float* bq = (const float*)d_in[2];
    const float* Wk = (const float*)d_in[3];
    const float* bk = (const float*)d_in[4];
    const float* Wv = (const float*)d_in[5];
    const float* bv = (const float*)d_in[6];
    const float* Wo = (const float*)d_in[7];
    const float* bo = (const float*)d_in[8];
    float* out = (float*)d_out;

    __half *xh, *wth, *qh, *kh, *vh, *vth, *ctxh;
    cudaGetSymbolAddress((void**)&xh,   g_xh);
    cudaGetSymbolAddress((void**)&wth,  g_wth);
    cudaGetSymbolAddress((void**)&qh,   g_qh);
    cudaGetSymbolAddress((void**)&kh,   g_kh);
    cudaGetSymbolAddress((void**)&vh,   g_vh);
    cudaGetSymbolAddress((void**)&vth,  g_vth);
    cudaGetSymbolAddress((void**)&ctxh, g_ctxh);
    __half* wtq = wth;
    __half* wtk = wth + DIM * DIM;
    __half* wtv = wth + 2 * DIM * DIM;
    __half* wto = wth + 3 * DIM * DIM;

    // 1) prep: x -> fp16, W -> transposed fp16
    {
        int n2 = NTOK * DIM / 2;
        f2h_kernel<<<(n2 + 255) / 256, 256>>>(
            (const float2*)x, (__half2*)xh, n2);
        dim3 tb(32, 8), tg(DIM / 32, DIM / 32);
        transpose_h_kernel<<<tg, tb>>>(Wq, wtq);
        transpose_h_kernel<<<tg, tb>>>(Wk, wtk);
        transpose_h_kernel<<<tg, tb>>>(Wv, wtv);
        transpose_h_kernel<<<tg, tb>>>(Wo, wto);
    }

    cudaFuncSetAttribute(gemm_h_kernel,
                         cudaFuncAttributeMaxDynamicSharedMemorySize,
                         GEMM_SMEM_BYTES);

    // 2) fused QKV projections (fp16 outputs)
    {
        dim3 gg(DIM / 128, NTOK / 128, 3);
        gemm_h_kernel<<<gg, 256, GEMM_SMEM_BYTES>>>(
            xh, wtq, wtk, wtv, bq, bk, bv, qh, kh, vh, 1);
    }

    // 3) transpose V
    {
        dim3 tb(32, 8), tg(SEQ / 32, HDIM / 32, BATCH * HEADS);
        vt_transpose_h_kernel<<<tg, tb>>>(vh, vth);
    }

    // 4) attention
    cudaFuncSetAttribute(attn_h_kernel,
                         cudaFuncAttributeMaxDynamicSharedMemorySize,
                         ATTN_SMEM_BYTES);
    attn_h_kernel<<<dim3(SEQ / 128, HEADS, BATCH), 256, ATTN_SMEM_BYTES>>>(
        qh, kh, vth, ctxh);

    // 5) output projection (fp32 output)
    {
        dim3 gg(DIM / 128, NTOK / 128, 1);
        gemm_h_kernel<<<gg, 256, GEMM_SMEM_BYTES>>>(
            ctxh, wto, wto, wto, bo, bo, bo, out, out, out, 0);
    }
}

// round 8
// speedup vs baseline: 2.0961x; 1.0996x over previous
#include <cuda_runtime.h>
#include <cuda_fp16.h>
#include <math_constants.h>
#include <cstdint>

#define NTOK 4096      // B*S
#define DIM  1024
#define HEADS 16
#define HDIM 64
#define SEQ  2048
#define BATCH 2

// Scratch (allocation-free requirement -> __device__ globals), all fp16
__device__ __half g_xh[NTOK * DIM];
__device__ __half g_wh[4 * DIM * DIM];    // fp16 Wq,Wk,Wv,Wo (natural [K][N])
__device__ __half g_qh[NTOK * DIM];
__device__ __half g_kh[NTOK * DIM];
__device__ __half g_vh[NTOK * DIM];
__device__ __half g_ctxh[NTOK * DIM];

// ===========================================================================
// Helpers
// ===========================================================================
__device__ __forceinline__ float ex2f(float x) {
    float y;
    asm("ex2.approx.ftz.f32 %0, %1;" : "=f"(y) : "f"(x));
    return y;
}

#define CP_ASYNC16(smem_addr, gmem_ptr) \
    asm volatile("cp.async.cg.shared.global [%0], [%1], 16;" \
                 :: "r"((uint32_t)(smem_addr)), "l"(gmem_ptr) : "memory")
#define CP_COMMIT() asm volatile("cp.async.commit_group;" ::: "memory")
#define CP_WAIT(n)  asm volatile("cp.async.wait_group %0;" :: "n"(n) : "memory")

__device__ __forceinline__ uint32_t smem_u32(const void* p) {
    uint32_t a;
    asm("{ .reg .u64 t; cvta.to.shared.u64 t, %1; cvt.u32.u64 %0, t; }"
        : "=r"(a) : "l"(p));
    return a;
}

#define LDSM_X4(r0, r1, r2, r3, addr) \
    asm volatile("ldmatrix.sync.aligned.m8n8.x4.shared.b16 {%0,%1,%2,%3}, [%4];" \
                 : "=r"(r0), "=r"(r1), "=r"(r2), "=r"(r3) : "r"(addr))

#define LDSM_X4_T(r0, r1, r2, r3, addr) \
    asm volatile("ldmatrix.sync.aligned.m8n8.x4.trans.shared.b16 {%0,%1,%2,%3}, [%4];" \
                 : "=r"(r0), "=r"(r1), "=r"(r2), "=r"(r3) : "r"(addr))

// mma m16n8k16 fp16 in, fp32 accum
__device__ __forceinline__ void mma_f16(
    float* d, const uint32_t* a, const uint32_t* b)
{
    asm volatile(
        "mma.sync.aligned.m16n8k16.row.col.f32.f16.f16.f32 "
        "{%0,%1,%2,%3}, {%4,%5,%6,%7}, {%8,%9}, {%0,%1,%2,%3};"
        : "+f"(d[0]), "+f"(d[1]), "+f"(d[2]), "+f"(d[3])
        : "r"(a[0]), "r"(a[1]), "r"(a[2]), "r"(a[3]),
          "r"(b[0]), "r"(b[1]));
}

// ===========================================================================
// fp16 GEMM:  C[z] = A @ W[z] + bias[z]
//  A:[4096,1024] fp16 row-major;  W:[K][N] fp16 natural layout, consumed via
//  ldmatrix.trans (no pre-transpose).  CTA tile 128x128, BK=32, 256 thr
//  (8 warps of 32x64), 3-stage cp.async ring (CP_WAIT(1)), 2 CTAs/SM.
//  A smem stride 40 halves, B smem stride 136 halves -> conflict-free LDSM.
// ===========================================================================
#define GDIM 1024
#define BKH 32
#define ASTRH 40
#define BSTRH 136
#define A_STH (128 * ASTRH)          // 5120 halves
#define B_STH (BKH * BSTRH)          // 4352 halves
#define STH   (A_STH + B_STH)        // 9472 halves per stage
#define NSTG  3
#define GEMM_SMEM_BYTES (NSTG * STH * 2)   // 56832 B

__global__ void __launch_bounds__(256, 2) gemm_h_kernel(
    const __half* __restrict__ A,
    const __half* __restrict__ W0, const __half* __restrict__ W1,
    const __half* __restrict__ W2,
    const float* __restrict__ b0p, const float* __restrict__ b1p,
    const float* __restrict__ b2p,
    void* __restrict__ C0, void* __restrict__ C1, void* __restrict__ C2,
    int out_half)
{
    extern __shared__ __align__(16) __half smh[];

    const int z = blockIdx.z;
    const __half* W    = (z == 0) ? W0 : (z == 1) ? W1 : W2;
    const float*  bias = (z == 0) ? b0p : (z == 1) ? b1p : b2p;
    void*         Cv   = (z == 0) ? C0 : (z == 1) ? C1 : C2;

    const int tid  = threadIdx.x;
    const int wid  = tid >> 5;
    const int lane = tid & 31;
    const int g    = lane >> 2;
    const int t    = lane & 3;
    const int lrow = lane & 7;
    const int sub  = lane >> 3;      // 0..3
    const int wm   = wid >> 1;       // 0..3
    const int wn   = wid & 1;        // 0..1

    const int brow = blockIdx.y * 128;
    const int bcol = blockIdx.x * 128;

    const uint32_t smu = smem_u32(smh);

    // A ldmatrix coords (row-major A, non-trans)
    const int arow_l = wm * 32 + lrow + ((sub & 1) << 3);   // + mi*16
    const int akoff  = (sub >> 1) << 3;                     // + ks*16
    // B ldmatrix coords ([k][n] W tile, trans)
    const int btrow  = lrow + ((sub & 1) << 3);             // k row (+ ks*16)
    const int bncol  = (sub >> 1) << 3;                     // n offset (+ pi*16)

    // A loader: 128 rows x 32 halves; 2 chunks/thread
    const int alr  = tid >> 1;
    const int alcb = (tid & 1) * 16;
    const __half* Asrc = A + (size_t)(brow + alr) * GDIM + alcb;
    const uint32_t aloff = (uint32_t)(alr * ASTRH + alcb) * 2u;
    // B loader: 32 rows x 128 halves; 2 chunks/thread
    //  chunk idx = tid + i*256 -> row = idx>>4 (0..31), c = idx&15
    const int blr = tid >> 4;
    const int blc = (tid & 15) * 8;

    auto load_stage = [&](int s, int kt) {
        const int k0 = kt * BKH;
        const uint32_t base = smu + (uint32_t)(s * STH) * 2u;
        CP_ASYNC16(base + aloff,      Asrc + k0);
        CP_ASYNC16(base + aloff + 16, Asrc + k0 + 8);
        const uint32_t bbase = base + (uint32_t)A_STH * 2u;
#pragma unroll
        for (int i = 0; i < 2; i++) {
            const int r = blr + i * 16;
            CP_ASYNC16(bbase + (uint32_t)(r * BSTRH + blc) * 2u,
                       W + (size_t)(k0 + r) * GDIM + bcol + blc);
        }
        CP_COMMIT();
    };

    float acc[2][8][4];
#pragma unroll
    for (int mi = 0; mi < 2; mi++)
#pragma unroll
        for (int ni = 0; ni < 8; ni++)
#pragma unroll
            for (int c = 0; c < 4; c++) acc[mi][ni][c] = 0.f;

    load_stage(0, 0);
    load_stage(1, 1);

    const int NKT = GDIM / BKH;   // 32
    for (int kt = 0; kt < NKT; ++kt) {
        const int cur = kt % NSTG;
        CP_WAIT(1);
        __syncthreads();

        const uint32_t aBase = smu + (uint32_t)(cur * STH) * 2u;
        const uint32_t bBase = aBase + (uint32_t)A_STH * 2u;

#pragma unroll
        for (int ks = 0; ks < 2; ks++) {
            uint32_t af[2][4];
#pragma unroll
            for (int mi = 0; mi < 2; mi++) {
                const uint32_t a = aBase +
                    (uint32_t)((arow_l + mi * 16) * ASTRH + ks * 16 + akoff) * 2u;
                LDSM_X4(af[mi][0], af[mi][1], af[mi][2], af[mi][3], a);
            }
            uint32_t bf[8][2];
#pragma unroll
            for (int pi = 0; pi < 4; pi++) {
                const uint32_t a = bBase +
                    (uint32_t)((ks * 16 + btrow) * BSTRH +
                               wn * 64 + pi * 16 + bncol) * 2u;
                uint32_t r0, r1, r2, r3;
                LDSM_X4_T(r0, r1, r2, r3, a);
                bf[2 * pi][0] = r0; bf[2 * pi][1] = r1;
                bf[2 * pi + 1][0] = r2; bf[2 * pi + 1][1] = r3;
            }
#pragma unroll
            for (int mi = 0; mi < 2; mi++)
#pragma unroll
                for (int ni = 0; ni < 8; ni++)
                    mma_f16(acc[mi][ni], af[mi], bf[ni]);
        }

        if (kt + 2 < NKT) load_stage((kt + 2) % NSTG, kt + 2);
    }

    // Epilogue
#pragma unroll
    for (int ni = 0; ni < 8; ni++) {
        const int col = bcol + wn * 64 + ni * 8 + t * 2;
        const float2 bv = *reinterpret_cast<const float2*>(&bias[col]);
#pragma unroll
        for (int mi = 0; mi < 2; mi++) {
            const int r0 = brow + wm * 32 + mi * 16 + g;
            float2 v0, v1;
            v0.x = acc[mi][ni][0] + bv.x;
            v0.y = acc[mi][ni][1] + bv.y;
            v1.x = acc[mi][ni][2] + bv.x;
            v1.y = acc[mi][ni][3] + bv.y;
            if (out_half) {
                __half* C = (__half*)Cv;
                *reinterpret_cast<__half2*>(&C[(size_t)r0 * GDIM + col]) =
                    __floats2half2_rn(v0.x, v0.y);
                *reinterpret_cast<__half2*>(&C[(size_t)(r0 + 8) * GDIM + col]) =
                    __floats2half2_rn(v1.x, v1.y);
            } else {
                float* C = (float*)Cv;
                *reinterpret_cast<float2*>(&C[(size_t)r0 * GDIM + col])       = v0;
                *reinterpret_cast<float2*>(&C[(size_t)(r0 + 8) * GDIM + col]) = v1;
            }
        }
    }
}

// ===========================================================================
// Fused prep: fp32 -> fp16 for x and all four W's in ONE launch.
//  z = 0..3 -> W[z] (524288 half2);  z = 4 -> x (4 x 524288 half2)
// ===========================================================================
#define PREP_CHUNK (DIM * DIM / 2)   // 524288 half2 per W

__global__ void f2h_multi_kernel(
    const float2* __restrict__ x,
    const float2* __restrict__ Wq, const float2* __restrict__ Wk,
    const float2* __restrict__ Wv, const float2* __restrict__ Wo,
    __half2* __restrict__ xh, __half2* __restrict__ wh)
{
    const int z = blockIdx.z;
    const int i = blockIdx.x * blockDim.x + threadIdx.x;
    if (z < 4) {
        const float2* src = (z == 0) ? Wq : (z == 1) ? Wk : (z == 2) ? Wv : Wo;
        float2 v = src[i];
        wh[(size_t)z * PREP_CHUNK + i] = __floats2half2_rn(v.x, v.y);
    } else {
#pragma unroll
        for (int j = 0; j < 4; j++) {
            const size_t idx = (size_t)i + (size_t)j * PREP_CHUNK;
            float2 v = x[idx];
            xh[idx] = __floats2half2_rn(v.x, v.y);
        }
    }
}

// ===========================================================================
// fp16 flash attention.  Per CTA: 128 queries x one (b,h); 8 warps of 16 rows.
// 64-key tiles, double-buffered K/V, V consumed via ldmatrix.trans directly
// from its natural [S][D] layout (no pre-transpose). fp32 softmax.
// ===========================================================================
#define QSTR 72                       // halves per smem row; (4*r)%32 distinct
#define SP_OFF   (128 * QSTR)
#define SK_OFF   (2 * 128 * QSTR)
#define KVBUF    (64 * QSTR)
#define SV_OFF   (SK_OFF + 2 * KVBUF)
#define ATTN_SMEM_BYTES ((2 * 128 * QSTR + 4 * KVBUF) * 2)   // 73728 B

__global__ void __launch_bounds__(256, 2) attn_h_kernel(
    const __half* __restrict__ Q, const __half* __restrict__ K,
    const __half* __restrict__ V, __half* __restrict__ O)
{
    extern __shared__ __align__(16) __half smh[];
    const uint32_t smu = smem_u32(smh);
    __half* sP = smh + SP_OFF;

    const int tid  = threadIdx.x;
    const int wid  = tid >> 5;
    const int lane = tid & 31;
    const int g    = lane >> 2;
    const int t    = lane & 3;
    const int lrow = lane & 7;
    const int sub  = lane >> 3;
    const int wm   = wid * 16;

    const int q0 = blockIdx.x * 128;
    const int h  = blockIdx.y;
    const int b  = blockIdx.z;
    const size_t rowbase = (size_t)b * SEQ;
    const int colbase = h * HDIM;

    const float cscale = 0.125f * 1.4426950408889634f;  // 1/sqrt(64)*log2(e)

    // ldmatrix per-thread coordinates
    const int arow_l = lrow + ((sub & 1) << 3);          // A rows (+ base)
    const int akoff  = (sub >> 1) << 3;                  // A k offset (+ ks*16)
    const int bn_l   = lrow + ((sub >> 1) << 3);         // K-op n (+ pi*16)
    const int bkoff  = (sub & 1) << 3;                   // K-op k offset (+ ks*16)
    const int vtrow  = lrow + ((sub & 1) << 3);          // V trans k-row (+ ks*16)
    const int vncol  = (sub >> 1) << 3;                  // V trans n off (+ pi*16)

    // ---- stage Q (raw fp16, 128 rows x 64 halves): 4 chunks per thread ----
    {
        const int qr  = tid >> 1;
        const int qc  = (tid & 1) * 32;
        const __half* src = &Q[(rowbase + q0 + qr) * DIM + colbase + qc];
        const uint32_t dst = smu + (uint32_t)(qr * QSTR + qc) * 2u;
#pragma unroll
        for (int i = 0; i < 4; i++)
            CP_ASYNC16(dst + i * 16, src + i * 8);
    }

    // ---- K/V tile loader: both [64 keys][64 dh], identical coalesced form ----
    const int kr = tid >> 2;
    const int kc = (tid & 3) * 16;
    auto load_kv = [&](int s, int t0) {
        const uint32_t kdst = smu + (uint32_t)((SK_OFF + s * KVBUF) + kr * QSTR + kc) * 2u;
        const uint32_t vdst = smu + (uint32_t)((SV_OFF + s * KVBUF) + kr * QSTR + kc) * 2u;
        const __half* ksrc = &K[(rowbase + t0 + kr) * DIM + colbase + kc];
        const __half* vsrc = &V[(rowbase + t0 + kr) * DIM + colbase + kc];
        CP_ASYNC16(kdst,      ksrc);
        CP_ASYNC16(kdst + 16, ksrc + 8);
        CP_ASYNC16(vdst,      vsrc);
        CP_ASYNC16(vdst + 16, vsrc + 8);
        CP_COMMIT();
    };

    load_kv(0, 0);   // commits Q loads too

    float m0 = -CUDART_INF_F, m1 = -CUDART_INF_F;
    float l0 = 0.f, l1 = 0.f;
    float accO[8][4];
#pragma unroll
    for (int ni = 0; ni < 8; ni++)
#pragma unroll
        for (int c = 0; c < 4; c++) accO[ni][c] = 0.f;

    for (int t0 = 0; t0 < SEQ; t0 += 64) {
        const int cur = (t0 >> 6) & 1;
        CP_WAIT(0);
        __syncthreads();
        if (t0 + 64 < SEQ) load_kv(cur ^ 1, t0 + 64);

        const uint32_t kBase = smu + (uint32_t)(SK_OFF + cur * KVBUF) * 2u;
        const uint32_t vBase = smu + (uint32_t)(SV_OFF + cur * KVBUF) * 2u;

        // ---- S = Q @ K^T (fp32 accum) ----
        float sfr[8][4];
#pragma unroll
        for (int ni = 0; ni < 8; ni++)
#pragma unroll
            for (int c = 0; c < 4; c++) sfr[ni][c] = 0.f;

#pragma unroll
        for (int ks = 0; ks < 4; ks++) {
            uint32_t af[4];
            {
                const uint32_t a = smu +
                    (uint32_t)((wm + arow_l) * QSTR + ks * 16 + akoff) * 2u;
                LDSM_X4(af[0], af[1], af[2], af[3], a);
            }
#pragma unroll
            for (int pi = 0; pi < 4; pi++) {
                const uint32_t a = kBase +
                    (uint32_t)((bn_l + pi * 16) * QSTR + ks * 16 + bkoff) * 2u;
                uint32_t r0, r1, r2, r3;
                LDSM_X4(r0, r1, r2, r3, a);
                uint32_t bf0[2] = { r0, r1 }, bf1[2] = { r2, r3 };
                mma_f16(sfr[2 * pi],     af, bf0);
                mma_f16(sfr[2 * pi + 1], af, bf1);
            }
        }

        // ---- online softmax (scale applied to fp32 scores) ----
        float mt0 = sfr[0][0], mt1 = sfr[0][2];
#pragma unroll
        for (int ni = 0; ni < 8; ni++) {
            mt0 = fmaxf(mt0, fmaxf(sfr[ni][0], sfr[ni][1]));
            mt1 = fmaxf(mt1, fmaxf(sfr[ni][2], sfr[ni][3]));
        }
        mt0 = fmaxf(mt0, __shfl_xor_sync(0xffffffffu, mt0, 1));
        mt0 = fmaxf(mt0, __shfl_xor_sync(0xffffffffu, mt0, 2));
        mt1 = fmaxf(mt1, __shfl_xor_sync(0xffffffffu, mt1, 1));
        mt1 = fmaxf(mt1, __shfl_xor_sync(0xffffffffu, mt1, 2));
        mt0 *= cscale;
        mt1 *= cscale;

        const float mn0 = fmaxf(m0, mt0);
        const float mn1 = fmaxf(m1, mt1);
        const float al0 = ex2f(m0 - mn0);
        const float al1 = ex2f(m1 - mn1);
        m0 = mn0; m1 = mn1;

        float lt0 = 0.f, lt1 = 0.f;
#pragma unroll
        for (int ni = 0; ni < 8; ni++) {
            float p0 = ex2f(sfr[ni][0] * cscale - mn0);
            float p1 = ex2f(sfr[ni][1] * cscale - mn0);
            float p2 = ex2f(sfr[ni][2] * cscale - mn1);
            float p3 = ex2f(sfr[ni][3] * cscale - mn1);
            lt0 += p0 + p1;
            lt1 += p2 + p3;
            *reinterpret_cast<__half2*>(&sP[(wm + g) * QSTR + ni * 8 + 2 * t]) =
                __floats2half2_rn(p0, p1);
            *reinterpret_cast<__half2*>(&sP[(wm + g + 8) * QSTR + ni * 8 + 2 * t]) =
                __floats2half2_rn(p2, p3);
        }
        lt0 += __shfl_xor_sync(0xffffffffu, lt0, 1);
        lt0 += __shfl_xor_sync(0xffffffffu, lt0, 2);
        lt1 += __shfl_xor_sync(0xffffffffu, lt1, 1);
        lt1 += __shfl_xor_sync(0xffffffffu, lt1, 2);
        l0 = l0 * al0 + lt0;
        l1 = l1 * al1 + lt1;

#pragma unroll
        for (int ni = 0; ni < 8; ni++) {
            accO[ni][0] *= al0; accO[ni][1] *= al0;
            accO[ni][2] *= al1; accO[ni][3] *= al1;
        }
        __syncwarp();   // sP rows are warp-private

        // ---- O += P @ V  (V [keys][dh] via trans ldmatrix) ----
#pragma unroll
        for (int ks = 0; ks < 4; ks++) {
            uint32_t pf[4];
            {
                const uint32_t a = smu +
                    (uint32_t)(SP_OFF * 2) +
                    (uint32_t)((wm + arow_l) * QSTR + ks * 16 + akoff) * 2u;
                LDSM_X4(pf[0], pf[1], pf[2], pf[3], a);
            }
#pragma unroll
            for (int pi = 0; pi < 4; pi++) {
                const uint32_t a = vBase +
                    (uint32_t)((ks * 16 + vtrow) * QSTR + pi * 16 + vncol) * 2u;
                uint32_t r0, r1, r2, r3;
                LDSM_X4_T(r0, r1, r2, r3, a);
                uint32_t bf0[2] = { r0, r1 }, bf1[2] = { r2, r3 };
                mma_f16(accO[2 * pi],     pf, bf0);
                mma_f16(accO[2 * pi + 1], pf, bf1);
            }
        }
        __syncwarp();   // done reading sP before next tile overwrites it
    }

    // ---- normalize + write ctx (fp16, feeds Wo GEMM) ----
    const float inv0 = 1.f / l0;
    const float inv1 = 1.f / l1;
#pragma unroll
    for (int ni = 0; ni < 8; ni++) {
        const int col = colbase + ni * 8 + 2 * t;
        *reinterpret_cast<__half2*>(&O[(rowbase + q0 + wm + g) * DIM + col]) =
            __floats2half2_rn(accO[ni][0] * inv0, accO[ni][1] * inv0);
        *reinterpret_cast<__half2*>(&O[(rowbase + q0 + wm + g + 8) * DIM + col]) =
            __floats2half2_rn(accO[ni][2] * inv1, accO[ni][3] * inv1);
    }
}

// ===========================================================================
extern "C" void kernel_launch(void* const* d_in, const int* in_sizes, int n_in,
                              void* d_out, int out_size)
{
    const float* x  = (const float*)d_in[0];
    const float* Wq = (const float*)d_in[1];
    const float* bq = (const float*)d_in[2];
    const float* Wk = (const float*)d_in[3];
    const float* bk = (const float*)d_in[4];
    const float* Wv = (const float*)d_in[5];
    const float* bv = (const float*)d_in[6];
    const float* Wo = (const float*)d_in[7];
    const float* bo = (const float*)d_in[8];
    float* out = (float*)d_out;

    __half *xh, *wh, *qh, *kh, *vh, *ctxh;
    cudaGetSymbolAddress((void**)&xh,   g_xh);
    cudaGetSymbolAddress((void**)&wh,   g_wh);
    cudaGetSymbolAddress((void**)&qh,   g_qh);
    cudaGetSymbolAddress((void**)&kh,   g_kh);
    cudaGetSymbolAddress((void**)&vh,   g_vh);
    cudaGetSymbolAddress((void**)&ctxh, g_ctxh);
    __half* wqh = wh;
    __half* wkh = wh + DIM * DIM;
    __half* wvh = wh + 2 * DIM * DIM;
    __half* woh = wh + 3 * DIM * DIM;

    // 1) fused prep: x and all W's -> fp16, one launch
    {
        dim3 pg(PREP_CHUNK / 256, 1, 5);
        f2h_multi_kernel<<<pg, 256>>>(
            (const float2*)x, (const float2*)Wq, (const float2*)Wk,
            (const float2*)Wv, (const float2*)Wo,
            (__half2*)xh, (__half2*)wh);
    }

    cudaFuncSetAttribute(gemm_h_kernel,
                         cudaFuncAttributeMaxDynamicSharedMemorySize,
                         GEMM_SMEM_BYTES);

    // 2) fused QKV projections (fp16 outputs)
    {
        dim3 gg(DIM / 128, NTOK / 128, 3);
        gemm_h_kernel<<<gg, 256, GEMM_SMEM_BYTES>>>(
            xh, wqh, wkh, wvh, bq, bk, bv, qh, kh, vh, 1);
    }

    // 3) attention (V consumed in natural layout via ldmatrix.trans)
    cudaFuncSetAttribute(attn_h_kernel,
                         cudaFuncAttributeMaxDynamicSharedMemorySize,
                         ATTN_SMEM_BYTES);
    attn_h_kernel<<<dim3(SEQ / 128, HEADS, BATCH), 256, ATTN_SMEM_BYTES>>>(
        qh, kh, vh, ctxh);

    // 4) output projection (fp32 output)
    {
        dim3 gg(DIM / 128, NTOK / 128, 1);
        gemm_h_kernel<<<gg, 256, GEMM_SMEM_BYTES>>>(
            ctxh, woh, woh, woh, bo, bo, bo, out, out, out, 0);
    }
}

// round 9
// speedup vs baseline: 2.2242x; 1.0611x over previous
#include <cuda_runtime.h>
#include <cuda_fp16.h>
#include <math_constants.h>
#include <cstdint>

#define NTOK 4096      // B*S
#define DIM  1024
#define HEADS 16
#define HDIM 64
#define SEQ  2048
#define BATCH 2

// Scratch (allocation-free requirement -> __device__ globals), all fp16
__device__ __half g_xh[NTOK * DIM];
__device__ __half g_wh[4 * DIM * DIM];    // fp16 Wq,Wk,Wv,Wo (natural [K][N])
__device__ __half g_qh[NTOK * DIM];
__device__ __half g_kh[NTOK * DIM];
__device__ __half g_vh[NTOK * DIM];
__device__ __half g_ctxh[NTOK * DIM];

// ===========================================================================
// Helpers
// ===========================================================================
__device__ __forceinline__ float ex2f(float x) {
    float y;
    asm("ex2.approx.ftz.f32 %0, %1;" : "=f"(y) : "f"(x));
    return y;
}

#define CP_ASYNC16(smem_addr, gmem_ptr) \
    asm volatile("cp.async.cg.shared.global [%0], [%1], 16;" \
                 :: "r"((uint32_t)(smem_addr)), "l"(gmem_ptr) : "memory")
#define CP_COMMIT() asm volatile("cp.async.commit_group;" ::: "memory")
#define CP_WAIT(n)  asm volatile("cp.async.wait_group %0;" :: "n"(n) : "memory")

__device__ __forceinline__ uint32_t smem_u32(const void* p) {
    uint32_t a;
    asm("{ .reg .u64 t; cvta.to.shared.u64 t, %1; cvt.u32.u64 %0, t; }"
        : "=r"(a) : "l"(p));
    return a;
}

#define LDSM_X4(r0, r1, r2, r3, addr) \
    asm volatile("ldmatrix.sync.aligned.m8n8.x4.shared.b16 {%0,%1,%2,%3}, [%4];" \
                 : "=r"(r0), "=r"(r1), "=r"(r2), "=r"(r3) : "r"(addr))

#define LDSM_X4_T(r0, r1, r2, r3, addr) \
    asm volatile("ldmatrix.sync.aligned.m8n8.x4.trans.shared.b16 {%0,%1,%2,%3}, [%4];" \
                 : "=r"(r0), "=r"(r1), "=r"(r2), "=r"(r3) : "r"(addr))

// mma m16n8k16 fp16 in, fp32 accum
__device__ __forceinline__ void mma_f16(
    float* d, const uint32_t* a, const uint32_t* b)
{
    asm volatile(
        "mma.sync.aligned.m16n8k16.row.col.f32.f16.f16.f32 "
        "{%0,%1,%2,%3}, {%4,%5,%6,%7}, {%8,%9}, {%0,%1,%2,%3};"
        : "+f"(d[0]), "+f"(d[1]), "+f"(d[2]), "+f"(d[3])
        : "r"(a[0]), "r"(a[1]), "r"(a[2]), "r"(a[3]),
          "r"(b[0]), "r"(b[1]));
}

// ===========================================================================
// fp16 GEMM:  C[z] = A @ W[z] + bias[z]
//  A:[4096,1024] fp16 row-major;  W:[K][N] fp16 natural layout, consumed via
//  ldmatrix.trans.  CTA tile 128x128, BK=64 (64 MMAs per barrier), 256 thr
//  (8 warps of 32x64), 3-stage cp.async ring (CP_WAIT(1)), 2 CTAs/SM.
//  A smem stride 72 halves, B smem stride 136 halves -> conflict-free LDSM.
// ===========================================================================
#define GDIM 1024
#define BKH 64
#define ASTRH 72
#define BSTRH 136
#define A_STH (128 * ASTRH)          // 9216 halves
#define B_STH (BKH * BSTRH)          // 8704 halves
#define STH   (A_STH + B_STH)        // 17920 halves per stage
#define NSTG  3
#define GEMM_SMEM_BYTES (NSTG * STH * 2)   // 107520 B

__global__ void __launch_bounds__(256, 2) gemm_h_kernel(
    const __half* __restrict__ A,
    const __half* __restrict__ W0, const __half* __restrict__ W1,
    const __half* __restrict__ W2,
    const float* __restrict__ b0p, const float* __restrict__ b1p,
    const float* __restrict__ b2p,
    void* __restrict__ C0, void* __restrict__ C1, void* __restrict__ C2,
    int out_half)
{
    extern __shared__ __align__(16) __half smh[];

    const int z = blockIdx.z;
    const __half* W    = (z == 0) ? W0 : (z == 1) ? W1 : W2;
    const float*  bias = (z == 0) ? b0p : (z == 1) ? b1p : b2p;
    void*         Cv   = (z == 0) ? C0 : (z == 1) ? C1 : C2;

    const int tid  = threadIdx.x;
    const int wid  = tid >> 5;
    const int lane = tid & 31;
    const int g    = lane >> 2;
    const int t    = lane & 3;
    const int lrow = lane & 7;
    const int sub  = lane >> 3;      // 0..3
    const int wm   = wid >> 1;       // 0..3
    const int wn   = wid & 1;        // 0..1

    const int brow = blockIdx.y * 128;
    const int bcol = blockIdx.x * 128;

    const uint32_t smu = smem_u32(smh);

    // A ldmatrix coords (row-major A, non-trans)
    const int arow_l = wm * 32 + lrow + ((sub & 1) << 3);   // + mi*16
    const int akoff  = (sub >> 1) << 3;                     // + ks*16
    // B ldmatrix coords ([k][n] W tile, trans)
    const int btrow  = lrow + ((sub & 1) << 3);             // k row (+ ks*16)
    const int bncol  = (sub >> 1) << 3;                     // n offset (+ pi*16)

    // A loader: 128 rows x 64 halves; 4 chunks/thread
    //  chunk idx = tid + i*256 -> row = idx>>3 (0..127), c = idx&7
    const int alr = tid >> 3;
    const int alc = (tid & 7) * 8;
    const __half* Asrc = A + (size_t)(brow + alr) * GDIM + alc;
    // B loader: 64 rows x 128 halves; 4 chunks/thread
    //  chunk idx = tid + i*256 -> row = idx>>4 (0..63), c = idx&15
    const int blr = tid >> 4;
    const int blc = (tid & 15) * 8;

    auto load_stage = [&](int s, int kt) {
        const int k0 = kt * BKH;
        const uint32_t abase = smu + (uint32_t)(s * STH) * 2u;
        const uint32_t bbase = abase + (uint32_t)A_STH * 2u;
#pragma unroll
        for (int i = 0; i < 4; i++) {
            const int ra = alr + i * 32;
            CP_ASYNC16(abase + (uint32_t)(ra * ASTRH + alc) * 2u,
                       Asrc + (size_t)(i * 32) * GDIM + k0);
            const int rb = blr + i * 16;
            CP_ASYNC16(bbase + (uint32_t)(rb * BSTRH + blc) * 2u,
                       W + (size_t)(k0 + rb) * GDIM + bcol + blc);
        }
        CP_COMMIT();
    };

    float acc[2][8][4];
#pragma unroll
    for (int mi = 0; mi < 2; mi++)
#pragma unroll
        for (int ni = 0; ni < 8; ni++)
#pragma unroll
            for (int c = 0; c < 4; c++) acc[mi][ni][c] = 0.f;

    load_stage(0, 0);
    load_stage(1, 1);

    const int NKT = GDIM / BKH;   // 16
    for (int kt = 0; kt < NKT; ++kt) {
        const int cur = kt % NSTG;
        CP_WAIT(1);
        __syncthreads();

        const uint32_t aBase = smu + (uint32_t)(cur * STH) * 2u;
        const uint32_t bBase = aBase + (uint32_t)A_STH * 2u;

#pragma unroll
        for (int ks = 0; ks < 4; ks++) {
            uint32_t af[2][4];
#pragma unroll
            for (int mi = 0; mi < 2; mi++) {
                const uint32_t a = aBase +
                    (uint32_t)((arow_l + mi * 16) * ASTRH + ks * 16 + akoff) * 2u;
                LDSM_X4(af[mi][0], af[mi][1], af[mi][2], af[mi][3], a);
            }
            uint32_t bf[8][2];
#pragma unroll
            for (int pi = 0; pi < 4; pi++) {
                const uint32_t a = bBase +
                    (uint32_t)((ks * 16 + btrow) * BSTRH +
                               wn * 64 + pi * 16 + bncol) * 2u;
                uint32_t r0, r1, r2, r3;
                LDSM_X4_T(r0, r1, r2, r3, a);
                bf[2 * pi][0] = r0; bf[2 * pi][1] = r1;
                bf[2 * pi + 1][0] = r2; bf[2 * pi + 1][1] = r3;
            }
#pragma unroll
            for (int mi = 0; mi < 2; mi++)
#pragma unroll
                for (int ni = 0; ni < 8; ni++)
                    mma_f16(acc[mi][ni], af[mi], bf[ni]);
        }

        if (kt + 2 < NKT) load_stage((kt + 2) % NSTG, kt + 2);
    }

    // Epilogue
#pragma unroll
    for (int ni = 0; ni < 8; ni++) {
        const int col = bcol + wn * 64 + ni * 8 + t * 2;
        const float2 bv = *reinterpret_cast<const float2*>(&bias[col]);
#pragma unroll
        for (int mi = 0; mi < 2; mi++) {
            const int r0 = brow + wm * 32 + mi * 16 + g;
            float2 v0, v1;
            v0.x = acc[mi][ni][0] + bv.x;
            v0.y = acc[mi][ni][1] + bv.y;
            v1.x = acc[mi][ni][2] + bv.x;
            v1.y = acc[mi][ni][3] + bv.y;
            if (out_half) {
                __half* C = (__half*)Cv;
                *reinterpret_cast<__half2*>(&C[(size_t)r0 * GDIM + col]) =
                    __floats2half2_rn(v0.x, v0.y);
                *reinterpret_cast<__half2*>(&C[(size_t)(r0 + 8) * GDIM + col]) =
                    __floats2half2_rn(v1.x, v1.y);
            } else {
                float* C = (float*)Cv;
                *reinterpret_cast<float2*>(&C[(size_t)r0 * GDIM + col])       = v0;
                *reinterpret_cast<float2*>(&C[(size_t)(r0 + 8) * GDIM + col]) = v1;
            }
        }
    }
}

// ===========================================================================
// Fused prep: fp32 -> fp16 for x and all four W's in ONE launch.
// ===========================================================================
#define PREP_CHUNK (DIM * DIM / 2)   // 524288 half2 per W

__global__ void f2h_multi_kernel(
    const float2* __restrict__ x,
    const float2* __restrict__ Wq, const float2* __restrict__ Wk,
    const float2* __restrict__ Wv, const float2* __restrict__ Wo,
    __half2* __restrict__ xh, __half2* __restrict__ wh)
{
    const int z = blockIdx.z;
    const int i = blockIdx.x * blockDim.x + threadIdx.x;
    if (z < 4) {
        const float2* src = (z == 0) ? Wq : (z == 1) ? Wk : (z == 2) ? Wv : Wo;
        float2 v = src[i];
        wh[(size_t)z * PREP_CHUNK + i] = __floats2half2_rn(v.x, v.y);
    } else {
#pragma unroll
        for (int j = 0; j < 4; j++) {
            const size_t idx = (size_t)i + (size_t)j * PREP_CHUNK;
            float2 v = x[idx];
            xh[idx] = __floats2half2_rn(v.x, v.y);
        }
    }
}

// ===========================================================================
// fp16 flash attention (unchanged from R8).
// ===========================================================================
#define QSTR 72
#define SP_OFF   (128 * QSTR)
#define SK_OFF   (2 * 128 * QSTR)
#define KVBUF    (64 * QSTR)
#define SV_OFF   (SK_OFF + 2 * KVBUF)
#define ATTN_SMEM_BYTES ((2 * 128 * QSTR + 4 * KVBUF) * 2)   // 73728 B

__global__ void __launch_bounds__(256, 2) attn_h_kernel(
    const __half* __restrict__ Q, const __half* __restrict__ K,
    const __half* __restrict__ V, __half* __restrict__ O)
{
    extern __shared__ __align__(16) __half smh[];
    const uint32_t smu = smem_u32(smh);
    __half* sP = smh + SP_OFF;

    const int tid  = threadIdx.x;
    const int wid  = tid >> 5;
    const int lane = tid & 31;
    const int g    = lane >> 2;
    const int t    = lane & 3;
    const int lrow = lane & 7;
    const int sub  = lane >> 3;
    const int wm   = wid * 16;

    const int q0 = blockIdx.x * 128;
    const int h  = blockIdx.y;
    const int b  = blockIdx.z;
    const size_t rowbase = (size_t)b * SEQ;
    const int colbase = h * HDIM;

    const float cscale = 0.125f * 1.4426950408889634f;  // 1/sqrt(64)*log2(e)

    const int arow_l = lrow + ((sub & 1) << 3);
    const int akoff  = (sub >> 1) << 3;
    const int bn_l   = lrow + ((sub >> 1) << 3);
    const int bkoff  = (sub & 1) << 3;
    const int vtrow  = lrow + ((sub & 1) << 3);
    const int vncol  = (sub >> 1) << 3;

    // ---- stage Q ----
    {
        const int qr  = tid >> 1;
        const int qc  = (tid & 1) * 32;
        const __half* src = &Q[(rowbase + q0 + qr) * DIM + colbase + qc];
        const uint32_t dst = smu + (uint32_t)(qr * QSTR + qc) * 2u;
#pragma unroll
        for (int i = 0; i < 4; i++)
            CP_ASYNC16(dst + i * 16, src + i * 8);
    }

    const int kr = tid >> 2;
    const int kc = (tid & 3) * 16;
    auto load_kv = [&](int s, int t0) {
        const uint32_t kdst = smu + (uint32_t)((SK_OFF + s * KVBUF) + kr * QSTR + kc) * 2u;
        const uint32_t vdst = smu + (uint32_t)((SV_OFF + s * KVBUF) + kr * QSTR + kc) * 2u;
        const __half* ksrc = &K[(rowbase + t0 + kr) * DIM + colbase + kc];
        const __half* vsrc = &V[(rowbase + t0 + kr) * DIM + colbase + kc];
        CP_ASYNC16(kdst,      ksrc);
        CP_ASYNC16(kdst + 16, ksrc + 8);
        CP_ASYNC16(vdst,      vsrc);
        CP_ASYNC16(vdst + 16, vsrc + 8);
        CP_COMMIT();
    };

    load_kv(0, 0);

    float m0 = -CUDART_INF_F, m1 = -CUDART_INF_F;
    float l0 = 0.f, l1 = 0.f;
    float accO[8][4];
#pragma unroll
    for (int ni = 0; ni < 8; ni++)
#pragma unroll
        for (int c = 0; c < 4; c++) accO[ni][c] = 0.f;

    for (int t0 = 0; t0 < SEQ; t0 += 64) {
        const int cur = (t0 >> 6) & 1;
        CP_WAIT(0);
        __syncthreads();
        if (t0 + 64 < SEQ) load_kv(cur ^ 1, t0 + 64);

        const uint32_t kBase = smu + (uint32_t)(SK_OFF + cur * KVBUF) * 2u;
        const uint32_t vBase = smu + (uint32_t)(SV_OFF + cur * KVBUF) * 2u;

        float sfr[8][4];
#pragma unroll
        for (int ni = 0; ni < 8; ni++)
#pragma unroll
            for (int c = 0; c < 4; c++) sfr[ni][c] = 0.f;

#pragma unroll
        for (int ks = 0; ks < 4; ks++) {
            uint32_t af[4];
            {
                const uint32_t a = smu +
                    (uint32_t)((wm + arow_l) * QSTR + ks * 16 + akoff) * 2u;
                LDSM_X4(af[0], af[1], af[2], af[3], a);
            }
#pragma unroll
            for (int pi = 0; pi < 4; pi++) {
                const uint32_t a = kBase +
                    (uint32_t)((bn_l + pi * 16) * QSTR + ks * 16 + bkoff) * 2u;
                uint32_t r0, r1, r2, r3;
                LDSM_X4(r0, r1, r2, r3, a);
                uint32_t bf0[2] = { r0, r1 }, bf1[2] = { r2, r3 };
                mma_f16(sfr[2 * pi],     af, bf0);
                mma_f16(sfr[2 * pi + 1], af, bf1);
            }
        }

        float mt0 = sfr[0][0], mt1 = sfr[0][2];
#pragma unroll
        for (int ni = 0; ni < 8; ni++) {
            mt0 = fmaxf(mt0, fmaxf(sfr[ni][0], sfr[ni][1]));
            mt1 = fmaxf(mt1, fmaxf(sfr[ni][2], sfr[ni][3]));
        }
        mt0 = fmaxf(mt0, __shfl_xor_sync(0xffffffffu, mt0, 1));
        mt0 = fmaxf(mt0, __shfl_xor_sync(0xffffffffu, mt0, 2));
        mt1 = fmaxf(mt1, __shfl_xor_sync(0xffffffffu, mt1, 1));
        mt1 = fmaxf(mt1, __shfl_xor_sync(0xffffffffu, mt1, 2));
        mt0 *= cscale;
        mt1 *= cscale;

        const float mn0 = fmaxf(m0, mt0);
        const float mn1 = fmaxf(m1, mt1);
        const float al0 = ex2f(m0 - mn0);
        const float al1 = ex2f(m1 - mn1);
        m0 = mn0; m1 = mn1;

        float lt0 = 0.f, lt1 = 0.f;
#pragma unroll
        for (int ni = 0; ni < 8; ni++) {
            float p0 = ex2f(sfr[ni][0] * cscale - mn0);
            float p1 = ex2f(sfr[ni][1] * cscale - mn0);
            float p2 = ex2f(sfr[ni][2] * cscale - mn1);
            float p3 = ex2f(sfr[ni][3] * cscale - mn1);
            lt0 += p0 + p1;
            lt1 += p2 + p3;
            *reinterpret_cast<__half2*>(&sP[(wm + g) * QSTR + ni * 8 + 2 * t]) =
                __floats2half2_rn(p0, p1);
            *reinterpret_cast<__half2*>(&sP[(wm + g + 8) * QSTR + ni * 8 + 2 * t]) =
                __floats2half2_rn(p2, p3);
        }
        lt0 += __shfl_xor_sync(0xffffffffu, lt0, 1);
        lt0 += __shfl_xor_sync(0xffffffffu, lt0, 2);
        lt1 += __shfl_xor_sync(0xffffffffu, lt1, 1);
        lt1 += __shfl_xor_sync(0xffffffffu, lt1, 2);
        l0 = l0 * al0 + lt0;
        l1 = l1 * al1 + lt1;

#pragma unroll
        for (int ni = 0; ni < 8; ni++) {
            accO[ni][0] *= al0; accO[ni][1] *= al0;
            accO[ni][2] *= al1; accO[ni][3] *= al1;
        }
        __syncwarp();

#pragma unroll
        for (int ks = 0; ks < 4; ks++) {
            uint32_t pf[4];
            {
                const uint32_t a = smu +
                    (uint32_t)(SP_OFF * 2) +
                    (uint32_t)((wm + arow_l) * QSTR + ks * 16 + akoff) * 2u;
                LDSM_X4(pf[0], pf[1], pf[2], pf[3], a);
            }
#pragma unroll
            for (int pi = 0; pi < 4; pi++) {
                const uint32_t a = vBase +
                    (uint32_t)((ks * 16 + vtrow) * QSTR + pi * 16 + vncol) * 2u;
                uint32_t r0, r1, r2, r3;
                LDSM_X4_T(r0, r1, r2, r3, a);
                uint32_t bf0[2] = { r0, r1 }, bf1[2] = { r2, r3 };
                mma_f16(accO[2 * pi],     pf, bf0);
                mma_f16(accO[2 * pi + 1], pf, bf1);
            }
        }
        __syncwarp();
    }

    const float inv0 = 1.f / l0;
    const float inv1 = 1.f / l1;
#pragma unroll
    for (int ni = 0; ni < 8; ni++) {
        const int col = colbase + ni * 8 + 2 * t;
        *reinterpret_cast<__half2*>(&O[(rowbase + q0 + wm + g) * DIM + col]) =
            __floats2half2_rn(accO[ni][0] * inv0, accO[ni][1] * inv0);
        *reinterpret_cast<__half2*>(&O[(rowbase + q0 + wm + g + 8) * DIM + col]) =
            __floats2half2_rn(accO[ni][2] * inv1, accO[ni][3] * inv1);
    }
}

// ===========================================================================
extern "C" void kernel_launch(void* const* d_in, const int* in_sizes, int n_in,
                              void* d_out, int out_size)
{
    const float* x  = (const float*)d_in[0];
    const float* Wq = (const float*)d_in[1];
    const float* bq = (const float*)d_in[2];
    const float* Wk = (const float*)d_in[3];
    const float* bk = (const float*)d_in[4];
    const float* Wv = (const float*)d_in[5];
    const float* bv = (const float*)d_in[6];
    const float* Wo = (const float*)d_in[7];
    const float* bo = (const float*)d_in[8];
    float* out = (float*)d_out;

    __half *xh, *wh, *qh, *kh, *vh, *ctxh;
    cudaGetSymbolAddress((void**)&xh,   g_xh);
    cudaGetSymbolAddress((void**)&wh,   g_wh);
    cudaGetSymbolAddress((void**)&qh,   g_qh);
    cudaGetSymbolAddress((void**)&kh,   g_kh);
    cudaGetSymbolAddress((void**)&vh,   g_vh);
    cudaGetSymbolAddress((void**)&ctxh, g_ctxh);
    __half* wqh = wh;
    __half* wkh = wh + DIM * DIM;
    __half* wvh = wh + 2 * DIM * DIM;
    __half* woh = wh + 3 * DIM * DIM;

    // 1) fused prep: x and all W's -> fp16, one launch
    {
        dim3 pg(PREP_CHUNK / 256, 1, 5);
        f2h_multi_kernel<<<pg, 256>>>(
            (const float2*)x, (const float2*)Wq, (const float2*)Wk,
            (const float2*)Wv, (const float2*)Wo,
            (__half2*)xh, (__half2*)wh);
    }

    cudaFuncSetAttribute(gemm_h_kernel,
                         cudaFuncAttributeMaxDynamicSharedMemorySize,
                         GEMM_SMEM_BYTES);

    // 2) fused QKV projections (fp16 outputs)
    {
        dim3 gg(DIM / 128, NTOK / 128, 3);
        gemm_h_kernel<<<gg, 256, GEMM_SMEM_BYTES>>>(
            xh, wqh, wkh, wvh, bq, bk, bv, qh, kh, vh, 1);
    }

    // 3) attention
    cudaFuncSetAttribute(attn_h_kernel,
                         cudaFuncAttributeMaxDynamicSharedMemorySize,
                         ATTN_SMEM_BYTES);
    attn_h_kernel<<<dim3(SEQ / 128, HEADS, BATCH), 256, ATTN_SMEM_BYTES>>>(
        qh, kh, vh, ctxh);

    // 4) output projection (fp32 output)
    {
        dim3 gg(DIM / 128, NTOK / 128, 1);
        gemm_h_kernel<<<gg, 256, GEMM_SMEM_BYTES>>>(
            ctxh, woh, woh, woh, bo, bo, bo, out, out, out, 0);
    }
}